// round 10
// baseline (speedup 1.0000x reference)
#include <cuda_runtime.h>
#include <cuda_bf16.h>
#include <cstdint>

// Problem constants
#define D_MODEL 1024
#define SEQ     2048
#define BATCH   2
#define HEADS   16
#define DKH     64
#define MROWS   (BATCH*SEQ)          // 4096
#define NX      (MROWS*D_MODEL)      // 2^22
#define NW      (D_MODEL*D_MODEL)    // 2^20

// ---------------------------------------------------------------------------
// Scratch (device globals — no allocation allowed)
// ---------------------------------------------------------------------------
__device__ __nv_bfloat16 g_xh[3][NX];
__device__ __nv_bfloat16 g_xl[3][NX];
__device__ __nv_bfloat16 g_wh[4][NW];
__device__ __nv_bfloat16 g_wl[4][NW];
__device__ __nv_bfloat16 g_qkvh[3][BATCH*HEADS*SEQ*DKH];
__device__ __nv_bfloat16 g_qkvl[3][BATCH*HEADS*SEQ*DKH];
__device__ __nv_bfloat16 g_aoh[NX];
__device__ __nv_bfloat16 g_aol[NX];

// ---------------------------------------------------------------------------
// PTX helpers
// ---------------------------------------------------------------------------
__device__ __forceinline__ uint32_t smem_to_u32(const void* p) {
    uint32_t a;
    asm("{ .reg .u64 t; cvta.to.shared.u64 t, %1; cvt.u32.u64 %0, t; }"
        : "=r"(a) : "l"(p));
    return a;
}

__device__ __forceinline__ void mma16816(float* c, const uint32_t* a, const uint32_t* b)
{
    asm volatile(
        "mma.sync.aligned.m16n8k16.row.col.f32.bf16.bf16.f32 "
        "{%0,%1,%2,%3}, {%4,%5,%6,%7}, {%8,%9}, {%0,%1,%2,%3};"
        : "+f"(c[0]), "+f"(c[1]), "+f"(c[2]), "+f"(c[3])
        : "r"(a[0]), "r"(a[1]), "r"(a[2]), "r"(a[3]), "r"(b[0]), "r"(b[1]));
}

__device__ __forceinline__ void ldsm_x4(uint32_t* r, uint32_t addr)
{
    asm volatile("ldmatrix.sync.aligned.m8n8.x4.shared.b16 {%0,%1,%2,%3}, [%4];"
        : "=r"(r[0]), "=r"(r[1]), "=r"(r[2]), "=r"(r[3]) : "r"(addr));
}

__device__ __forceinline__ void ldsm_x4_t(uint32_t* r, uint32_t addr)
{
    asm volatile("ldmatrix.sync.aligned.m8n8.x4.trans.shared.b16 {%0,%1,%2,%3}, [%4];"
        : "=r"(r[0]), "=r"(r[1]), "=r"(r[2]), "=r"(r[3]) : "r"(addr));
}

__device__ __forceinline__ void cp16(uint32_t saddr, const void* g) {
    asm volatile("cp.async.cg.shared.global [%0], [%1], 16;" :: "r"(saddr), "l"(g));
}
__device__ __forceinline__ void cp_commit() {
    asm volatile("cp.async.commit_group;");
}
template<int N> __device__ __forceinline__ void cp_wait() {
    asm volatile("cp.async.wait_group %0;" :: "n"(N));
}

__device__ __forceinline__ void pack_hl(float a, float b, uint32_t& hi, uint32_t& lo)
{
    __nv_bfloat162 h = __floats2bfloat162_rn(a, b);
    float ra = a - __bfloat162float(h.x);
    float rb = b - __bfloat162float(h.y);
    __nv_bfloat162 l = __floats2bfloat162_rn(ra, rb);
    hi = *reinterpret_cast<uint32_t*>(&h);
    lo = *reinterpret_cast<uint32_t*>(&l);
}

// ---------------------------------------------------------------------------
// Fused fp32 -> bf16 (hi, lo) split
// ---------------------------------------------------------------------------
__global__ __launch_bounds__(256) void splitk_all(
    const float* __restrict__ q,  const float* __restrict__ k,
    const float* __restrict__ v,  const float* __restrict__ Wq,
    const float* __restrict__ Wk, const float* __restrict__ Wv,
    const float* __restrict__ Wo)
{
    const size_t total4 = (size_t)(3*NX + 4*NW) / 4;
    for (size_t ch = (size_t)blockIdx.x*blockDim.x + threadIdx.x; ch < total4;
         ch += (size_t)gridDim.x*blockDim.x) {
        const size_t i = ch*4;
        const float* src;
        __nv_bfloat16 *hi, *lo;
        size_t off;
        if (i < (size_t)3*NX) {
            const int w = (int)(i >> 22);
            off = i & (NX - 1);
            src = (w == 0) ? q : (w == 1) ? k : v;
            hi = g_xh[w]; lo = g_xl[w];
        } else {
            const size_t j = i - (size_t)3*NX;
            const int w = (int)(j >> 20);
            off = j & (NW - 1);
            src = (w == 0) ? Wq : (w == 1) ? Wk : (w == 2) ? Wv : Wo;
            hi = g_wh[w]; lo = g_wl[w];
        }
        float4 vv = *(const float4*)(src + off);
        uint32_t h0, l0, h1, l1;
        pack_hl(vv.x, vv.y, h0, l0);
        pack_hl(vv.z, vv.w, h1, l1);
        *(uint32_t*)(hi + off)     = h0;
        *(uint32_t*)(hi + off + 2) = h1;
        *(uint32_t*)(lo + off)     = l0;
        *(uint32_t*)(lo + off + 2) = l1;
    }
}

// ---------------------------------------------------------------------------
// mma.sync GEMM: 128x128 CTA, 4 warps (64x64 per warp), 3-stage cp.async.
// Warp-tile doubling raises smem-fragment reuse 8 -> 24 MACs/byte.
// ---------------------------------------------------------------------------
#define GTILE_B   8192             // 128 rows * 64 B
#define GBUF_B    (4*GTILE_B)      // 32768 (Ahi,Alo,Whi,Wlo)
#define GEMM_SMEM (3*GBUF_B)       // 98304; x2 CTAs = 196608

__device__ __forceinline__ uint32_t gswz(int row, int c16) {
    return (uint32_t)row*64 + (uint32_t)((c16 ^ ((row >> 1) & 3)) * 16);
}

__device__ __forceinline__ void gemm_fill(
    const __nv_bfloat16* const* srcs, uint32_t stage_base, int kc, int row)
{
    const size_t g = (size_t)row*D_MODEL + kc;
    #pragma unroll
    for (int t = 0; t < 4; t++)
        #pragma unroll
        for (int c = 0; c < 4; c++)
            cp16(stage_base + t*GTILE_B + gswz(row, c), srcs[t] + g + c*8);
}

__device__ __forceinline__ void gemm_body(
    const __nv_bfloat16* Ah, const __nv_bfloat16* Al,
    const __nv_bfloat16* Wh, const __nv_bfloat16* Wl,
    const float* __restrict__ bias,
    float* __restrict__ outp, int dst, int bm, int bn, char* smem)
{
    const uint32_t sm0 = smem_to_u32(smem);
    const int tid  = threadIdx.x;          // 0..127
    const int lane = tid & 31;
    const int wid  = tid >> 5;             // 0..3
    const int wm = wid & 1;                // m offset 64*wm
    const int wn = wid >> 1;               // n offset 64*wn

    const __nv_bfloat16* srcs[4] = {
        Ah + (size_t)bm*128*D_MODEL,
        Al + (size_t)bm*128*D_MODEL,
        Wh + (size_t)bn*128*D_MODEL,
        Wl + (size_t)bn*128*D_MODEL };

    // prologue
    gemm_fill(srcs, sm0 + 0*GBUF_B, 0,  tid);
    cp_commit();
    gemm_fill(srcs, sm0 + 1*GBUF_B, 32, tid);
    cp_commit();

    const int a_row0 = wm*64 + (lane & 15);
    const int b_row0 = wn*64 + ((lane >> 4) & 1)*8 + (lane & 7);
    const int a_c16h = (lane >> 4) & 1;
    const int b_c16h = (lane >> 3) & 1;

    float acc[4][8][4] = {};

    for (int c = 0; c < 32; c++) {
        cp_wait<1>();
        __syncthreads();

        if (c < 30)
            gemm_fill(srcs, sm0 + ((c + 2) % 3)*GBUF_B, (c + 2)*32, tid);
        cp_commit();

        const uint32_t base = sm0 + (c % 3)*GBUF_B;
        #pragma unroll
        for (int ks = 0; ks < 2; ks++) {
            uint32_t ah[4][4], al[4][4];
            #pragma unroll
            for (int fm = 0; fm < 4; fm++) {
                const uint32_t ao = gswz(a_row0 + fm*16, ks*2 + a_c16h);
                ldsm_x4(ah[fm], base + 0*GTILE_B + ao);
                ldsm_x4(al[fm], base + 1*GTILE_B + ao);
            }
            #pragma unroll
            for (int p = 0; p < 4; p++) {
                const uint32_t bo = gswz(b_row0 + p*16, ks*2 + b_c16h);
                uint32_t bh[4], bl[4];
                ldsm_x4(bh, base + 2*GTILE_B + bo);
                ldsm_x4(bl, base + 3*GTILE_B + bo);
                #pragma unroll
                for (int q = 0; q < 2; q++) {
                    const int fn = p*2 + q;
                    #pragma unroll
                    for (int fm = 0; fm < 4; fm++) {
                        mma16816(acc[fm][fn], ah[fm], bh + q*2);
                        mma16816(acc[fm][fn], ah[fm], bl + q*2);
                        mma16816(acc[fm][fn], al[fm], bh + q*2);
                    }
                }
            }
        }
    }

    // Epilogue
    const int r4 = lane >> 2;
    const int kw = lane & 3;
    #pragma unroll
    for (int fm = 0; fm < 4; fm++) {
        #pragma unroll
        for (int fn = 0; fn < 8; fn++) {
            const int row = bm*128 + wm*64 + fm*16 + r4;
            const int col = bn*128 + wn*64 + fn*8 + kw*2;
            const float b0 = bias[col], b1 = bias[col+1];
            #pragma unroll
            for (int p = 0; p < 2; p++) {
                const int rr = row + p*8;
                const float vx = acc[fm][fn][p*2+0] + b0;
                const float vy = acc[fm][fn][p*2+1] + b1;
                if (dst < 3) {
                    const int b = rr >> 11, s = rr & 2047;
                    const int h = col >> 6, d = col & 63;
                    const size_t idx = (((size_t)(b*HEADS + h))*SEQ + s)*DKH + d;
                    uint32_t hi, lo;
                    pack_hl(vx, vy, hi, lo);
                    *(uint32_t*)(g_qkvh[dst] + idx) = hi;
                    *(uint32_t*)(g_qkvl[dst] + idx) = lo;
                } else {
                    float2 ov; ov.x = vx; ov.y = vy;
                    *(float2*)(outp + (size_t)rr*D_MODEL + col) = ov;
                }
            }
        }
    }
}

__global__ __launch_bounds__(128, 2) void gemm_qkv(
    const float* __restrict__ bq, const float* __restrict__ bk,
    const float* __restrict__ bv)
{
    extern __shared__ char smem[];
    const int z = blockIdx.z;
    const float* bias = (z == 0) ? bq : (z == 1) ? bk : bv;
    gemm_body(g_xh[z], g_xl[z], g_wh[z], g_wl[z], bias,
              nullptr, z, blockIdx.y, blockIdx.x, smem);
}

__global__ __launch_bounds__(128, 2) void gemm_out(
    const float* __restrict__ bo, float* __restrict__ outp)
{
    extern __shared__ char smem[];
    gemm_body(g_aoh, g_aol, g_wh[3], g_wl[3], bo,
              outp, 3, blockIdx.y, blockIdx.x, smem);
}

// ---------------------------------------------------------------------------
// Tensor-core flash attention: 4 warps x 32 q-rows, K/V frags reused over
// 2 m-frags (12 -> 24 MACs/byte).  3-stage cp.async, SW128 swizzle.
// ---------------------------------------------------------------------------
#define KVTILE_B   8192                // 64 rows * 128 B
#define KVBUF_B    (4*KVTILE_B)        // 32768
#define FLASH_SMEM (3*KVBUF_B)         // 98304; x2 CTAs = 196608

__device__ __forceinline__ uint32_t fswz(int row, int c16) {
    return (uint32_t)row*128 + (uint32_t)((c16 ^ (row & 7)) * 16);
}

__global__ __launch_bounds__(128, 2) void flash_mma(void)
{
    extern __shared__ char fsm[];
    const uint32_t sm0 = smem_to_u32(fsm);
    const int tid  = threadIdx.x;          // 0..127
    const int lane = tid & 31;
    const int wid  = tid >> 5;             // 0..3
    const int bh   = blockIdx.y;
    const int q0   = blockIdx.x * 128;
    const int b    = bh >> 4, h = bh & 15;

    const __nv_bfloat16* Qh = g_qkvh[0] + ((size_t)bh*SEQ + q0 + wid*32)*DKH;
    const __nv_bfloat16* Ql = g_qkvl[0] + ((size_t)bh*SEQ + q0 + wid*32)*DKH;
    const __nv_bfloat16* Kh = g_qkvh[1] + (size_t)bh*SEQ*DKH;
    const __nv_bfloat16* Kl = g_qkvl[1] + (size_t)bh*SEQ*DKH;
    const __nv_bfloat16* Vh = g_qkvh[2] + (size_t)bh*SEQ*DKH;
    const __nv_bfloat16* Vl = g_qkvl[2] + (size_t)bh*SEQ*DKH;

    const int r4 = lane >> 2;
    const int kw = lane & 3;

    // Q fragments: 2 m-frags x 4 k-slices, hi+lo
    uint32_t qh[2][4][4], ql[2][4][4];
    #pragma unroll
    for (int fm = 0; fm < 2; fm++) {
        #pragma unroll
        for (int ks = 0; ks < 4; ks++) {
            const int cb = ks*16 + kw*2;
            const size_t r0 = (size_t)(fm*16 + r4)*DKH;
            const size_t r1 = (size_t)(fm*16 + r4 + 8)*DKH;
            qh[fm][ks][0] = *(const uint32_t*)(Qh + r0 + cb);
            qh[fm][ks][1] = *(const uint32_t*)(Qh + r1 + cb);
            qh[fm][ks][2] = *(const uint32_t*)(Qh + r0 + cb + 8);
            qh[fm][ks][3] = *(const uint32_t*)(Qh + r1 + cb + 8);
            ql[fm][ks][0] = *(const uint32_t*)(Ql + r0 + cb);
            ql[fm][ks][1] = *(const uint32_t*)(Ql + r1 + cb);
            ql[fm][ks][2] = *(const uint32_t*)(Ql + r0 + cb + 8);
            ql[fm][ks][3] = *(const uint32_t*)(Ql + r1 + cb + 8);
        }
    }

    // KV loader: 128 threads, 2 rows/thread-pair; 16 cp16 per thread per tile-set
    const int  krow = tid >> 1;            // 0..63
    const int  khalf = tid & 1;            // c16 base 0 or 4
    const __nv_bfloat16* gsrc[4] = { Kh, Kl, Vh, Vl };

    const int k_row0 = ((lane >> 4) & 1)*8 + (lane & 7);
    const int k_c16h = (lane >> 3) & 1;
    const int v_row0 = ((lane >> 3) & 1)*8 + (lane & 7);
    const int v_c16h = (lane >> 4) & 1;

    float accO[2][8][4] = {};
    float lsum[2][2] = {};

    #pragma unroll
    for (int ktp = 0; ktp < 2; ktp++) {
        const uint32_t sb = sm0 + ktp*KVBUF_B;
        const size_t g = (size_t)ktp*64*DKH + (size_t)krow*DKH + khalf*32;
        #pragma unroll
        for (int t = 0; t < 4; t++)
            #pragma unroll
            for (int j = 0; j < 4; j++)
                cp16(sb + t*KVTILE_B + fswz(krow, khalf*4 + j), gsrc[t] + g + j*8);
        cp_commit();
    }

    #pragma unroll 1
    for (int kt = 0; kt < SEQ/64; kt++) {
        cp_wait<1>();
        __syncthreads();

        if (kt < SEQ/64 - 2) {
            const uint32_t sb = sm0 + ((kt+2) % 3)*KVBUF_B;
            const size_t g = (size_t)(kt+2)*64*DKH + (size_t)krow*DKH + khalf*32;
            #pragma unroll
            for (int t = 0; t < 4; t++)
                #pragma unroll
                for (int j = 0; j < 4; j++)
                    cp16(sb + t*KVTILE_B + fswz(krow, khalf*4 + j), gsrc[t] + g + j*8);
        }
        cp_commit();

        const uint32_t base = sm0 + (kt % 3)*KVBUF_B;

        // ---- scores: S = Q K^T  (32 x 64 per warp) ----
        float s[2][8][4] = {};
        #pragma unroll
        for (int ks = 0; ks < 4; ks++) {
            #pragma unroll
            for (int p = 0; p < 4; p++) {
                const uint32_t bo = fswz(p*16 + k_row0, ks*2 + k_c16h);
                uint32_t bhr[4], blr[4];
                ldsm_x4(bhr, base + 0*KVTILE_B + bo);
                ldsm_x4(blr, base + 1*KVTILE_B + bo);
                #pragma unroll
                for (int q = 0; q < 2; q++) {
                    #pragma unroll
                    for (int fm = 0; fm < 2; fm++) {
                        float* cc = s[fm][p*2 + q];
                        mma16816(cc, qh[fm][ks], bhr + q*2);
                        mma16816(cc, qh[fm][ks], blr + q*2);
                        mma16816(cc, ql[fm][ks], bhr + q*2);
                    }
                }
            }
        }

        // ---- P = exp(S); row sums ----
        #pragma unroll
        for (int fm = 0; fm < 2; fm++)
            #pragma unroll
            for (int f = 0; f < 8; f++) {
                s[fm][f][0] = __expf(s[fm][f][0]);
                s[fm][f][1] = __expf(s[fm][f][1]);
                s[fm][f][2] = __expf(s[fm][f][2]);
                s[fm][f][3] = __expf(s[fm][f][3]);
                lsum[fm][0] += s[fm][f][0] + s[fm][f][1];
                lsum[fm][1] += s[fm][f][2] + s[fm][f][3];
            }

        // ---- O += P V ----
        #pragma unroll
        for (int ks = 0; ks < 4; ks++) {
            uint32_t pah[2][4], pal[2][4];
            #pragma unroll
            for (int fm = 0; fm < 2; fm++) {
                const int f0 = 2*ks, f1 = 2*ks + 1;
                pack_hl(s[fm][f0][0], s[fm][f0][1], pah[fm][0], pal[fm][0]);
                pack_hl(s[fm][f0][2], s[fm][f0][3], pah[fm][1], pal[fm][1]);
                pack_hl(s[fm][f1][0], s[fm][f1][1], pah[fm][2], pal[fm][2]);
                pack_hl(s[fm][f1][2], s[fm][f1][3], pah[fm][3], pal[fm][3]);
            }
            #pragma unroll
            for (int p = 0; p < 4; p++) {
                const uint32_t vo = fswz(ks*16 + v_row0, p*2 + v_c16h);
                uint32_t vhr[4], vlr[4];
                ldsm_x4_t(vhr, base + 2*KVTILE_B + vo);
                ldsm_x4_t(vlr, base + 3*KVTILE_B + vo);
                #pragma unroll
                for (int q = 0; q < 2; q++) {
                    #pragma unroll
                    for (int fm = 0; fm < 2; fm++) {
                        float* cc = accO[fm][p*2 + q];
                        mma16816(cc, pah[fm], vhr + q*2);
                        mma16816(cc, pah[fm], vlr + q*2);
                        mma16816(cc, pal[fm], vhr + q*2);
                    }
                }
            }
        }
    }

    // ---- finalize ----
    #pragma unroll
    for (int fm = 0; fm < 2; fm++) {
        #pragma unroll
        for (int half = 0; half < 2; half++) {
            float v = lsum[fm][half];
            v += __shfl_xor_sync(0xffffffffu, v, 1);
            v += __shfl_xor_sync(0xffffffffu, v, 2);
            lsum[fm][half] = 1.f / v;
        }
    }

    #pragma unroll
    for (int fm = 0; fm < 2; fm++) {
        const size_t obase = ((size_t)b*SEQ + q0 + wid*32 + fm*16)*D_MODEL + h*DKH;
        #pragma unroll
        for (int f = 0; f < 8; f++) {
            const int d = f*8 + kw*2;
            uint32_t hi, lo;
            pack_hl(accO[fm][f][0]*lsum[fm][0], accO[fm][f][1]*lsum[fm][0], hi, lo);
            *(uint32_t*)(g_aoh + obase + (size_t)r4*D_MODEL + d) = hi;
            *(uint32_t*)(g_aol + obase + (size_t)r4*D_MODEL + d) = lo;
            pack_hl(accO[fm][f][2]*lsum[fm][1], accO[fm][f][3]*lsum[fm][1], hi, lo);
            *(uint32_t*)(g_aoh + obase + (size_t)(r4+8)*D_MODEL + d) = hi;
            *(uint32_t*)(g_aol + obase + (size_t)(r4+8)*D_MODEL + d) = lo;
        }
    }
}

// ---------------------------------------------------------------------------
// Launch
// ---------------------------------------------------------------------------
extern "C" void kernel_launch(void* const* d_in, const int* in_sizes, int n_in,
                              void* d_out, int out_size)
{
    const float* q  = (const float*)d_in[0];
    const float* k  = (const float*)d_in[1];
    const float* v  = (const float*)d_in[2];
    const float* Wq = (const float*)d_in[3];
    const float* bq = (const float*)d_in[4];
    const float* Wk = (const float*)d_in[5];
    const float* bk = (const float*)d_in[6];
    const float* Wv = (const float*)d_in[7];
    const float* bv = (const float*)d_in[8];
    const float* Wo = (const float*)d_in[9];
    const float* bo = (const float*)d_in[10];
    float* out = (float*)d_out;

    cudaFuncSetAttribute(gemm_qkv,  cudaFuncAttributeMaxDynamicSharedMemorySize, GEMM_SMEM);
    cudaFuncSetAttribute(gemm_out,  cudaFuncAttributeMaxDynamicSharedMemorySize, GEMM_SMEM);
    cudaFuncSetAttribute(flash_mma, cudaFuncAttributeMaxDynamicSharedMemorySize, FLASH_SMEM);

    splitk_all<<<8192, 256>>>(q, k, v, Wq, Wk, Wv, Wo);

    gemm_qkv<<<dim3(D_MODEL/128, MROWS/128, 3), 128, GEMM_SMEM>>>(bq, bk, bv);

    flash_mma<<<dim3(SEQ/128, BATCH*HEADS), 128, FLASH_SMEM>>>();

    gemm_out<<<dim3(D_MODEL/128, MROWS/128), 128, GEMM_SMEM>>>(bo, out);
}

// round 11
// speedup vs baseline: 1.2116x; 1.2116x over previous
#include <cuda_runtime.h>
#include <cuda_bf16.h>
#include <cuda_fp16.h>
#include <cstdint>

// Problem constants
#define D_MODEL 1024
#define SEQ     2048
#define BATCH   2
#define HEADS   16
#define DKH     64
#define MROWS   (BATCH*SEQ)          // 4096
#define NX      (MROWS*D_MODEL)      // 2^22
#define NW      (D_MODEL*D_MODEL)    // 2^20

// ---------------------------------------------------------------------------
// Scratch (device globals — no allocation allowed)
// ---------------------------------------------------------------------------
__device__ __half g_xh[3][NX];                    // q,k,v inputs fp16 hi
__device__ __half g_xl[3][NX];                    // fp16 lo
__device__ __half g_wh[4][NW];
__device__ __half g_wl[4][NW];
__device__ __nv_bfloat16 g_qkvh[3][BATCH*HEADS*SEQ*DKH];  // Q/K/V bf16 hi (flash)
__device__ __nv_bfloat16 g_qkvl[3][BATCH*HEADS*SEQ*DKH];  // bf16 lo
__device__ __half g_aoh[NX];                      // attention out fp16 hi
__device__ __half g_aol[NX];                      // fp16 lo

// ---------------------------------------------------------------------------
// PTX helpers
// ---------------------------------------------------------------------------
__device__ __forceinline__ uint32_t smem_to_u32(const void* p) {
    uint32_t a;
    asm("{ .reg .u64 t; cvta.to.shared.u64 t, %1; cvt.u32.u64 %0, t; }"
        : "=r"(a) : "l"(p));
    return a;
}

// bf16 MMA, f32 acc
__device__ __forceinline__ void mma16816(float* c, const uint32_t* a, const uint32_t* b)
{
    asm volatile(
        "mma.sync.aligned.m16n8k16.row.col.f32.bf16.bf16.f32 "
        "{%0,%1,%2,%3}, {%4,%5,%6,%7}, {%8,%9}, {%0,%1,%2,%3};"
        : "+f"(c[0]), "+f"(c[1]), "+f"(c[2]), "+f"(c[3])
        : "r"(a[0]), "r"(a[1]), "r"(a[2]), "r"(a[3]), "r"(b[0]), "r"(b[1]));
}

// fp16 MMA, f32 acc (main GEMM term)
__device__ __forceinline__ void mma16816f(float* c, const uint32_t* a, const uint32_t* b)
{
    asm volatile(
        "mma.sync.aligned.m16n8k16.row.col.f32.f16.f16.f32 "
        "{%0,%1,%2,%3}, {%4,%5,%6,%7}, {%8,%9}, {%0,%1,%2,%3};"
        : "+f"(c[0]), "+f"(c[1]), "+f"(c[2]), "+f"(c[3])
        : "r"(a[0]), "r"(a[1]), "r"(a[2]), "r"(a[3]), "r"(b[0]), "r"(b[1]));
}

// fp16 MMA, f16 acc (residual terms — hypothesized 2x rate)
__device__ __forceinline__ void mma16816h(uint32_t* c, const uint32_t* a, const uint32_t* b)
{
    asm volatile(
        "mma.sync.aligned.m16n8k16.row.col.f16.f16.f16.f16 "
        "{%0,%1}, {%2,%3,%4,%5}, {%6,%7}, {%0,%1};"
        : "+r"(c[0]), "+r"(c[1])
        : "r"(a[0]), "r"(a[1]), "r"(a[2]), "r"(a[3]), "r"(b[0]), "r"(b[1]));
}

__device__ __forceinline__ void ldsm_x4(uint32_t* r, uint32_t addr)
{
    asm volatile("ldmatrix.sync.aligned.m8n8.x4.shared.b16 {%0,%1,%2,%3}, [%4];"
        : "=r"(r[0]), "=r"(r[1]), "=r"(r[2]), "=r"(r[3]) : "r"(addr));
}

__device__ __forceinline__ void ldsm_x4_t(uint32_t* r, uint32_t addr)
{
    asm volatile("ldmatrix.sync.aligned.m8n8.x4.trans.shared.b16 {%0,%1,%2,%3}, [%4];"
        : "=r"(r[0]), "=r"(r[1]), "=r"(r[2]), "=r"(r[3]) : "r"(addr));
}

__device__ __forceinline__ void cp16(uint32_t saddr, const void* g) {
    asm volatile("cp.async.cg.shared.global [%0], [%1], 16;" :: "r"(saddr), "l"(g));
}
__device__ __forceinline__ void cp_commit() {
    asm volatile("cp.async.commit_group;");
}
template<int N> __device__ __forceinline__ void cp_wait() {
    asm volatile("cp.async.wait_group %0;" :: "n"(N));
}

// fp32 pair -> bf16x2 hi + lo
__device__ __forceinline__ void pack_hl(float a, float b, uint32_t& hi, uint32_t& lo)
{
    __nv_bfloat162 h = __floats2bfloat162_rn(a, b);
    float ra = a - __bfloat162float(h.x);
    float rb = b - __bfloat162float(h.y);
    __nv_bfloat162 l = __floats2bfloat162_rn(ra, rb);
    hi = *reinterpret_cast<uint32_t*>(&h);
    lo = *reinterpret_cast<uint32_t*>(&l);
}

// fp32 pair -> fp16x2 hi + lo
__device__ __forceinline__ void pack_hl16(float a, float b, uint32_t& hi, uint32_t& lo)
{
    __half2 h = __floats2half2_rn(a, b);
    float ra = a - __half2float(__low2half(h));
    float rb = b - __half2float(__high2half(h));
    __half2 l = __floats2half2_rn(ra, rb);
    hi = *reinterpret_cast<uint32_t*>(&h);
    lo = *reinterpret_cast<uint32_t*>(&l);
}

// ---------------------------------------------------------------------------
// Fused fp32 -> fp16 (hi, lo) split: all 7 tensors in one launch.
// ---------------------------------------------------------------------------
__global__ __launch_bounds__(256) void splitk_all(
    const float* __restrict__ q,  const float* __restrict__ k,
    const float* __restrict__ v,  const float* __restrict__ Wq,
    const float* __restrict__ Wk, const float* __restrict__ Wv,
    const float* __restrict__ Wo)
{
    const size_t total4 = (size_t)(3*NX + 4*NW) / 4;
    for (size_t ch = (size_t)blockIdx.x*blockDim.x + threadIdx.x; ch < total4;
         ch += (size_t)gridDim.x*blockDim.x) {
        const size_t i = ch*4;
        const float* src;
        __half *hi, *lo;
        size_t off;
        if (i < (size_t)3*NX) {
            const int w = (int)(i >> 22);
            off = i & (NX - 1);
            src = (w == 0) ? q : (w == 1) ? k : v;
            hi = g_xh[w]; lo = g_xl[w];
        } else {
            const size_t j = i - (size_t)3*NX;
            const int w = (int)(j >> 20);
            off = j & (NW - 1);
            src = (w == 0) ? Wq : (w == 1) ? Wk : (w == 2) ? Wv : Wo;
            hi = g_wh[w]; lo = g_wl[w];
        }
        float4 vv = *(const float4*)(src + off);
        uint32_t h0, l0, h1, l1;
        pack_hl16(vv.x, vv.y, h0, l0);
        pack_hl16(vv.z, vv.w, h1, l1);
        *(uint32_t*)(hi + off)     = h0;
        *(uint32_t*)(hi + off + 2) = h1;
        *(uint32_t*)(lo + off)     = l0;
        *(uint32_t*)(lo + off + 2) = l1;
    }
}

// ---------------------------------------------------------------------------
// fp16 mixed-acc GEMM: C = A @ W^T + bias.
// Main term AhWh -> f32 acc; residuals AhWl, AlWh -> f16 acc (2x-rate path).
// CTA 64x128, 8 warps (32x32 per warp), 3-stage cp.async, 2 CTAs/SM.
// Stage layout: Ah@0(4KB) Al@4096 Wh@8192(8KB) Wl@16384.
// ---------------------------------------------------------------------------
#define GSTAGE_B  24576
#define GEMM_SMEM (3*GSTAGE_B)     // 73728; x2 CTAs = 147456

__device__ __forceinline__ uint32_t gswz(int row, int c16) {
    return (uint32_t)row*64 + (uint32_t)((c16 ^ ((row >> 1) & 3)) * 16);
}

__device__ __forceinline__ void gemm_fill(
    const __half* Ah, const __half* Al,
    const __half* Wh, const __half* Wl,
    uint32_t stage, int kc, int tid)
{
    {   // A tiles: 64 rows x 64B, 1 cp16 each per thread
        const int row = tid >> 2, c = tid & 3;
        const size_t g = (size_t)row*D_MODEL + kc + c*8;
        const uint32_t s = stage + gswz(row, c);
        cp16(s,        Ah + g);
        cp16(s + 4096, Al + g);
    }
    {   // W tiles: 128 rows x 64B, 2 cp16 each per thread
        const int row = tid >> 1, c = (tid & 1)*2;
        const size_t g = (size_t)row*D_MODEL + kc + c*8;
        cp16(stage + 8192  + gswz(row, c),   Wh + g);
        cp16(stage + 8192  + gswz(row, c+1), Wh + g + 8);
        cp16(stage + 16384 + gswz(row, c),   Wl + g);
        cp16(stage + 16384 + gswz(row, c+1), Wl + g + 8);
    }
}

__device__ __forceinline__ void gemm_body(
    const __half* Ah, const __half* Al,
    const __half* Wh, const __half* Wl,
    const float* __restrict__ bias,
    float* __restrict__ outp, int dst, int bm, int bn, char* smem)
{
    const uint32_t sm0 = smem_to_u32(smem);
    const int tid  = threadIdx.x;
    const int lane = tid & 31;
    const int wid  = tid >> 5;
    const int wm = wid & 1;               // m offset 32*wm
    const int wn = wid >> 1;              // n offset 32*wn

    const __half* Ab  = Ah + (size_t)bm*64*D_MODEL;
    const __half* Alb = Al + (size_t)bm*64*D_MODEL;
    const __half* Wb  = Wh + (size_t)bn*128*D_MODEL;
    const __half* Wlb = Wl + (size_t)bn*128*D_MODEL;

    gemm_fill(Ab, Alb, Wb, Wlb, sm0 + 0*GSTAGE_B, 0,  tid);
    cp_commit();
    gemm_fill(Ab, Alb, Wb, Wlb, sm0 + 1*GSTAGE_B, 32, tid);
    cp_commit();

    const int a_row0 = wm*32 + (lane & 15);
    const int b_row0 = wn*32 + ((lane >> 4) & 1)*8 + (lane & 7);
    const int a_c16h = (lane >> 4) & 1;
    const int b_c16h = (lane >> 3) & 1;

    float    acc32[2][4][4] = {};
    uint32_t acc16[2][4][2] = {};

    for (int c = 0; c < 32; c++) {
        cp_wait<1>();
        __syncthreads();

        if (c < 30)
            gemm_fill(Ab, Alb, Wb, Wlb, sm0 + ((c + 2) % 3)*GSTAGE_B, (c + 2)*32, tid);
        cp_commit();

        const uint32_t base = sm0 + (c % 3)*GSTAGE_B;
        #pragma unroll
        for (int ks = 0; ks < 2; ks++) {
            uint32_t ah[2][4], al[2][4];
            #pragma unroll
            for (int fm = 0; fm < 2; fm++) {
                const uint32_t ao = gswz(a_row0 + fm*16, ks*2 + a_c16h);
                ldsm_x4(ah[fm], base + ao);
                ldsm_x4(al[fm], base + 4096 + ao);
            }
            #pragma unroll
            for (int p = 0; p < 2; p++) {
                const uint32_t bo = gswz(b_row0 + p*16, ks*2 + b_c16h);
                uint32_t bh[4], bl[4];
                ldsm_x4(bh, base + 8192  + bo);
                ldsm_x4(bl, base + 16384 + bo);
                #pragma unroll
                for (int q = 0; q < 2; q++) {
                    const int fn = p*2 + q;
                    #pragma unroll
                    for (int fm = 0; fm < 2; fm++) {
                        mma16816f(acc32[fm][fn], ah[fm], bh + q*2);  // main, f32
                        mma16816h(acc16[fm][fn], ah[fm], bl + q*2);  // res,  f16
                        mma16816h(acc16[fm][fn], al[fm], bh + q*2);  // res,  f16
                    }
                }
            }
        }
    }

    // Epilogue: C = acc32 + float(acc16) + bias
    const int r4 = lane >> 2;
    const int kw = lane & 3;
    #pragma unroll
    for (int fm = 0; fm < 2; fm++) {
        #pragma unroll
        for (int fn = 0; fn < 4; fn++) {
            const int row = bm*64 + wm*32 + fm*16 + r4;
            const int col = bn*128 + wn*32 + fn*8 + kw*2;
            const float b0 = bias[col], b1 = bias[col+1];
            #pragma unroll
            for (int p = 0; p < 2; p++) {
                const int rr = row + p*8;
                const __half2 h2 = *reinterpret_cast<const __half2*>(&acc16[fm][fn][p]);
                const float vx = acc32[fm][fn][p*2+0] + __half2float(__low2half(h2))  + b0;
                const float vy = acc32[fm][fn][p*2+1] + __half2float(__high2half(h2)) + b1;
                if (dst < 3) {
                    const int b = rr >> 11, s = rr & 2047;
                    const int h = col >> 6, d = col & 63;
                    const size_t idx = (((size_t)(b*HEADS + h))*SEQ + s)*DKH + d;
                    uint32_t hi, lo;
                    pack_hl(vx, vy, hi, lo);                 // bf16 for flash
                    *(uint32_t*)(g_qkvh[dst] + idx) = hi;
                    *(uint32_t*)(g_qkvl[dst] + idx) = lo;
                } else {
                    float2 ov; ov.x = vx; ov.y = vy;
                    *(float2*)(outp + (size_t)rr*D_MODEL + col) = ov;
                }
            }
        }
    }
}

__global__ __launch_bounds__(256, 2) void gemm_qkv(
    const float* __restrict__ bq, const float* __restrict__ bk,
    const float* __restrict__ bv)
{
    extern __shared__ char smem[];
    const int z = blockIdx.z;
    const float* bias = (z == 0) ? bq : (z == 1) ? bk : bv;
    gemm_body(g_xh[z], g_xl[z], g_wh[z], g_wl[z], bias,
              nullptr, z, blockIdx.y, blockIdx.x, smem);
}

__global__ __launch_bounds__(256, 2) void gemm_out(
    const float* __restrict__ bo, float* __restrict__ outp)
{
    extern __shared__ char smem[];
    gemm_body(g_aoh, g_aol, g_wh[3], g_wl[3], bo,
              outp, 3, blockIdx.y, blockIdx.x, smem);
}

// ---------------------------------------------------------------------------
// Tensor-core flash attention — UNCHANGED from the 621us version except the
// epilogue packs O as fp16 (for the fp16 output projection).
// ---------------------------------------------------------------------------
#define KVTILE_B   8192                // 64 rows * 128 B
#define KVBUF_B    (4*KVTILE_B)        // 32768
#define FLASH_SMEM (3*KVBUF_B)         // 98304; x2 CTAs = 196608

__device__ __forceinline__ uint32_t fswz(int row, int c16) {
    return (uint32_t)row*128 + (uint32_t)((c16 ^ (row & 7)) * 16);
}

__global__ __launch_bounds__(256, 2) void flash_mma(void)
{
    extern __shared__ char fsm[];
    const uint32_t sm0 = smem_to_u32(fsm);
    const int tid  = threadIdx.x;
    const int lane = tid & 31;
    const int wid  = tid >> 5;            // 0..7
    const int bh   = blockIdx.y;
    const int q0   = blockIdx.x * 128;
    const int b    = bh >> 4, h = bh & 15;

    const __nv_bfloat16* Qh = g_qkvh[0] + ((size_t)bh*SEQ + q0 + wid*16)*DKH;
    const __nv_bfloat16* Ql = g_qkvl[0] + ((size_t)bh*SEQ + q0 + wid*16)*DKH;
    const __nv_bfloat16* Kh = g_qkvh[1] + (size_t)bh*SEQ*DKH;
    const __nv_bfloat16* Kl = g_qkvl[1] + (size_t)bh*SEQ*DKH;
    const __nv_bfloat16* Vh = g_qkvh[2] + (size_t)bh*SEQ*DKH;
    const __nv_bfloat16* Vl = g_qkvl[2] + (size_t)bh*SEQ*DKH;

    const int r4 = lane >> 2;
    const int kw = lane & 3;

    uint32_t qh[4][4], ql[4][4];
    #pragma unroll
    for (int ks = 0; ks < 4; ks++) {
        const int cb = ks*16 + kw*2;
        qh[ks][0] = *(const uint32_t*)(Qh + (size_t)r4*DKH + cb);
        qh[ks][1] = *(const uint32_t*)(Qh + (size_t)(r4+8)*DKH + cb);
        qh[ks][2] = *(const uint32_t*)(Qh + (size_t)r4*DKH + cb + 8);
        qh[ks][3] = *(const uint32_t*)(Qh + (size_t)(r4+8)*DKH + cb + 8);
        ql[ks][0] = *(const uint32_t*)(Ql + (size_t)r4*DKH + cb);
        ql[ks][1] = *(const uint32_t*)(Ql + (size_t)(r4+8)*DKH + cb);
        ql[ks][2] = *(const uint32_t*)(Ql + (size_t)r4*DKH + cb + 8);
        ql[ks][3] = *(const uint32_t*)(Ql + (size_t)(r4+8)*DKH + cb + 8);
    }

    const int  krow = tid >> 2;
    const int  kq   = tid & 3;
    const size_t gkoff = (size_t)krow*DKH + kq*16;
    const uint32_t s0off = fswz(krow, kq*2);
    const uint32_t s1off = fswz(krow, kq*2 + 1);
    const __nv_bfloat16* gsrc[4] = { Kh, Kl, Vh, Vl };

    const int k_row0 = ((lane >> 4) & 1)*8 + (lane & 7);
    const int k_c16h = (lane >> 3) & 1;
    const int v_row0 = ((lane >> 3) & 1)*8 + (lane & 7);
    const int v_c16h = (lane >> 4) & 1;

    float accO[8][4] = {};
    float lsum0 = 0.f, lsum1 = 0.f;

    #pragma unroll
    for (int ktp = 0; ktp < 2; ktp++) {
        const size_t g = (size_t)ktp*64*DKH + gkoff;
        const uint32_t sb = sm0 + ktp*KVBUF_B;
        #pragma unroll
        for (int t = 0; t < 4; t++) {
            cp16(sb + t*KVTILE_B + s0off, gsrc[t] + g);
            cp16(sb + t*KVTILE_B + s1off, gsrc[t] + g + 8);
        }
        cp_commit();
    }

    #pragma unroll 1
    for (int kt = 0; kt < SEQ/64; kt++) {
        cp_wait<1>();
        __syncthreads();

        if (kt < SEQ/64 - 2) {
            const size_t g = (size_t)(kt+2)*64*DKH + gkoff;
            const uint32_t sb = sm0 + ((kt+2) % 3)*KVBUF_B;
            #pragma unroll
            for (int t = 0; t < 4; t++) {
                cp16(sb + t*KVTILE_B + s0off, gsrc[t] + g);
                cp16(sb + t*KVTILE_B + s1off, gsrc[t] + g + 8);
            }
        }
        cp_commit();

        const uint32_t base = sm0 + (kt % 3)*KVBUF_B;

        float s[8][4] = {};
        #pragma unroll
        for (int ks = 0; ks < 4; ks++) {
            #pragma unroll
            for (int pp = 0; pp < 4; pp += 2) {
                uint32_t bhr[2][4], blr[2][4];
                #pragma unroll
                for (int pi = 0; pi < 2; pi++) {
                    const uint32_t bo = fswz((pp + pi)*16 + k_row0, ks*2 + k_c16h);
                    ldsm_x4(bhr[pi], base + 0*KVTILE_B + bo);
                    ldsm_x4(blr[pi], base + 1*KVTILE_B + bo);
                }
                #pragma unroll
                for (int t = 0; t < 3; t++) {
                    const uint32_t* aa = (t == 2) ? ql[ks] : qh[ks];
                    #pragma unroll
                    for (int pi = 0; pi < 2; pi++) {
                        #pragma unroll
                        for (int q = 0; q < 2; q++) {
                            const uint32_t* bb = (t == 1) ? (blr[pi] + q*2)
                                                          : (bhr[pi] + q*2);
                            mma16816(s[(pp + pi)*2 + q], aa, bb);
                        }
                    }
                }
            }
        }

        #pragma unroll
        for (int f = 0; f < 8; f++) {
            s[f][0] = __expf(s[f][0]);
            s[f][1] = __expf(s[f][1]);
            s[f][2] = __expf(s[f][2]);
            s[f][3] = __expf(s[f][3]);
            lsum0 += s[f][0] + s[f][1];
            lsum1 += s[f][2] + s[f][3];
        }

        #pragma unroll
        for (int ks = 0; ks < 4; ks++) {
            uint32_t pah[4], pal[4];
            const int f0 = 2*ks, f1 = 2*ks + 1;
            pack_hl(s[f0][0], s[f0][1], pah[0], pal[0]);
            pack_hl(s[f0][2], s[f0][3], pah[1], pal[1]);
            pack_hl(s[f1][0], s[f1][1], pah[2], pal[2]);
            pack_hl(s[f1][2], s[f1][3], pah[3], pal[3]);
            #pragma unroll
            for (int pp = 0; pp < 4; pp += 2) {
                uint32_t vhr[2][4], vlr[2][4];
                #pragma unroll
                for (int pi = 0; pi < 2; pi++) {
                    const uint32_t vo = fswz(ks*16 + v_row0, (pp + pi)*2 + v_c16h);
                    ldsm_x4_t(vhr[pi], base + 2*KVTILE_B + vo);
                    ldsm_x4_t(vlr[pi], base + 3*KVTILE_B + vo);
                }
                #pragma unroll
                for (int t = 0; t < 3; t++) {
                    const uint32_t* aa = (t == 2) ? pal : pah;
                    #pragma unroll
                    for (int pi = 0; pi < 2; pi++) {
                        #pragma unroll
                        for (int q = 0; q < 2; q++) {
                            const uint32_t* bb = (t == 1) ? (vlr[pi] + q*2)
                                                          : (vhr[pi] + q*2);
                            mma16816(accO[(pp + pi)*2 + q], aa, bb);
                        }
                    }
                }
            }
        }
    }

    lsum0 += __shfl_xor_sync(0xffffffffu, lsum0, 1);
    lsum0 += __shfl_xor_sync(0xffffffffu, lsum0, 2);
    lsum1 += __shfl_xor_sync(0xffffffffu, lsum1, 1);
    lsum1 += __shfl_xor_sync(0xffffffffu, lsum1, 2);
    const float inv0 = 1.f / lsum0;
    const float inv1 = 1.f / lsum1;

    const size_t obase = ((size_t)b*SEQ + q0 + wid*16)*D_MODEL + h*DKH;
    #pragma unroll
    for (int f = 0; f < 8; f++) {
        const int d = f*8 + kw*2;
        uint32_t hi, lo;
        pack_hl16(accO[f][0]*inv0, accO[f][1]*inv0, hi, lo);
        *(uint32_t*)(g_aoh + obase + (size_t)r4*D_MODEL + d) = hi;
        *(uint32_t*)(g_aol + obase + (size_t)r4*D_MODEL + d) = lo;
        pack_hl16(accO[f][2]*inv1, accO[f][3]*inv1, hi, lo);
        *(uint32_t*)(g_aoh + obase + (size_t)(r4+8)*D_MODEL + d) = hi;
        *(uint32_t*)(g_aol + obase + (size_t)(r4+8)*D_MODEL + d) = lo;
    }
}

// ---------------------------------------------------------------------------
// Launch
// ---------------------------------------------------------------------------
extern "C" void kernel_launch(void* const* d_in, const int* in_sizes, int n_in,
                              void* d_out, int out_size)
{
    const float* q  = (const float*)d_in[0];
    const float* k  = (const float*)d_in[1];
    const float* v  = (const float*)d_in[2];
    const float* Wq = (const float*)d_in[3];
    const float* bq = (const float*)d_in[4];
    const float* Wk = (const float*)d_in[5];
    const float* bk = (const float*)d_in[6];
    const float* Wv = (const float*)d_in[7];
    const float* bv = (const float*)d_in[8];
    const float* Wo = (const float*)d_in[9];
    const float* bo = (const float*)d_in[10];
    float* out = (float*)d_out;

    cudaFuncSetAttribute(gemm_qkv,  cudaFuncAttributeMaxDynamicSharedMemorySize, GEMM_SMEM);
    cudaFuncSetAttribute(gemm_out,  cudaFuncAttributeMaxDynamicSharedMemorySize, GEMM_SMEM);
    cudaFuncSetAttribute(flash_mma, cudaFuncAttributeMaxDynamicSharedMemorySize, FLASH_SMEM);

    splitk_all<<<8192, 256>>>(q, k, v, Wq, Wk, Wv, Wo);

    gemm_qkv<<<dim3(D_MODEL/128, MROWS/64, 3), 256, GEMM_SMEM>>>(bq, bk, bv);

    flash_mma<<<dim3(SEQ/128, BATCH*HEADS), 256, FLASH_SMEM>>>();

    gemm_out<<<dim3(D_MODEL/128, MROWS/64), 256, GEMM_SMEM>>>(bo, out);
}

// round 13
// speedup vs baseline: 1.4150x; 1.1679x over previous
#include <cuda_runtime.h>
#include <cuda_bf16.h>
#include <cuda_fp16.h>
#include <cstdint>

// Problem constants
#define D_MODEL 1024
#define SEQ     2048
#define BATCH   2
#define HEADS   16
#define DKH     64
#define MROWS   (BATCH*SEQ)          // 4096
#define NX      (MROWS*D_MODEL)      // 2^22
#define NW      (D_MODEL*D_MODEL)    // 2^20

// ---------------------------------------------------------------------------
// Scratch (device globals — no allocation allowed)
// ---------------------------------------------------------------------------
__device__ __half g_xh[3][NX];                    // q,k,v inputs fp16 hi
__device__ __half g_xl[3][NX];                    // fp16 lo (lo unused for v)
__device__ __half g_wh[4][NW];
__device__ __half g_wl[4][NW];                    // lo unused for Wv, Wo
__device__ __nv_bfloat16 g_qkvh[3][BATCH*HEADS*SEQ*DKH];  // Q/K/V bf16 hi (flash)
__device__ __nv_bfloat16 g_qkvl[3][BATCH*HEADS*SEQ*DKH];  // bf16 lo
__device__ __half g_aoh[NX];                      // attention out fp16 (single)

// ---------------------------------------------------------------------------
// PTX helpers
// ---------------------------------------------------------------------------
__device__ __forceinline__ uint32_t smem_to_u32(const void* p) {
    uint32_t a;
    asm("{ .reg .u64 t; cvta.to.shared.u64 t, %1; cvt.u32.u64 %0, t; }"
        : "=r"(a) : "l"(p));
    return a;
}

// bf16 MMA, f32 acc (flash)
__device__ __forceinline__ void mma16816(float* c, const uint32_t* a, const uint32_t* b)
{
    asm volatile(
        "mma.sync.aligned.m16n8k16.row.col.f32.bf16.bf16.f32 "
        "{%0,%1,%2,%3}, {%4,%5,%6,%7}, {%8,%9}, {%0,%1,%2,%3};"
        : "+f"(c[0]), "+f"(c[1]), "+f"(c[2]), "+f"(c[3])
        : "r"(a[0]), "r"(a[1]), "r"(a[2]), "r"(a[3]), "r"(b[0]), "r"(b[1]));
}

// fp16 MMA, f32 acc (projections)
__device__ __forceinline__ void mma16816f(float* c, const uint32_t* a, const uint32_t* b)
{
    asm volatile(
        "mma.sync.aligned.m16n8k16.row.col.f32.f16.f16.f32 "
        "{%0,%1,%2,%3}, {%4,%5,%6,%7}, {%8,%9}, {%0,%1,%2,%3};"
        : "+f"(c[0]), "+f"(c[1]), "+f"(c[2]), "+f"(c[3])
        : "r"(a[0]), "r"(a[1]), "r"(a[2]), "r"(a[3]), "r"(b[0]), "r"(b[1]));
}

__device__ __forceinline__ void ldsm_x4(uint32_t* r, uint32_t addr)
{
    asm volatile("ldmatrix.sync.aligned.m8n8.x4.shared.b16 {%0,%1,%2,%3}, [%4];"
        : "=r"(r[0]), "=r"(r[1]), "=r"(r[2]), "=r"(r[3]) : "r"(addr));
}

__device__ __forceinline__ void ldsm_x4_t(uint32_t* r, uint32_t addr)
{
    asm volatile("ldmatrix.sync.aligned.m8n8.x4.trans.shared.b16 {%0,%1,%2,%3}, [%4];"
        : "=r"(r[0]), "=r"(r[1]), "=r"(r[2]), "=r"(r[3]) : "r"(addr));
}

__device__ __forceinline__ void cp16(uint32_t saddr, const void* g) {
    asm volatile("cp.async.cg.shared.global [%0], [%1], 16;" :: "r"(saddr), "l"(g));
}
__device__ __forceinline__ void cp_commit() {
    asm volatile("cp.async.commit_group;");
}
template<int N> __device__ __forceinline__ void cp_wait() {
    asm volatile("cp.async.wait_group %0;" :: "n"(N));
}

// fp32 pair -> bf16x2 hi + lo
__device__ __forceinline__ void pack_hl(float a, float b, uint32_t& hi, uint32_t& lo)
{
    __nv_bfloat162 h = __floats2bfloat162_rn(a, b);
    float ra = a - __bfloat162float(h.x);
    float rb = b - __bfloat162float(h.y);
    __nv_bfloat162 l = __floats2bfloat162_rn(ra, rb);
    hi = *reinterpret_cast<uint32_t*>(&h);
    lo = *reinterpret_cast<uint32_t*>(&l);
}

// fp32 pair -> fp16x2 hi + lo
__device__ __forceinline__ void pack_hl16(float a, float b, uint32_t& hi, uint32_t& lo)
{
    __half2 h = __floats2half2_rn(a, b);
    float ra = a - __half2float(__low2half(h));
    float rb = b - __half2float(__high2half(h));
    __half2 l = __floats2half2_rn(ra, rb);
    hi = *reinterpret_cast<uint32_t*>(&h);
    lo = *reinterpret_cast<uint32_t*>(&l);
}

// ---------------------------------------------------------------------------
// Fused fp32 -> fp16 (hi, lo) split: all 7 tensors in one launch.
// ---------------------------------------------------------------------------
__global__ __launch_bounds__(256) void splitk_all(
    const float* __restrict__ q,  const float* __restrict__ k,
    const float* __restrict__ v,  const float* __restrict__ Wq,
    const float* __restrict__ Wk, const float* __restrict__ Wv,
    const float* __restrict__ Wo)
{
    const size_t total4 = (size_t)(3*NX + 4*NW) / 4;
    for (size_t ch = (size_t)blockIdx.x*blockDim.x + threadIdx.x; ch < total4;
         ch += (size_t)gridDim.x*blockDim.x) {
        const size_t i = ch*4;
        const float* src;
        __half *hi, *lo;
        size_t off;
        if (i < (size_t)3*NX) {
            const int w = (int)(i >> 22);
            off = i & (NX - 1);
            src = (w == 0) ? q : (w == 1) ? k : v;
            hi = g_xh[w]; lo = g_xl[w];
        } else {
            const size_t j = i - (size_t)3*NX;
            const int w = (int)(j >> 20);
            off = j & (NW - 1);
            src = (w == 0) ? Wq : (w == 1) ? Wk : (w == 2) ? Wv : Wo;
            hi = g_wh[w]; lo = g_wl[w];
        }
        float4 vv = *(const float4*)(src + off);
        uint32_t h0, l0, h1, l1;
        pack_hl16(vv.x, vv.y, h0, l0);
        pack_hl16(vv.z, vv.w, h1, l1);
        *(uint32_t*)(hi + off)     = h0;
        *(uint32_t*)(hi + off + 2) = h1;
        *(uint32_t*)(lo + off)     = l0;
        *(uint32_t*)(lo + off + 2) = l1;
    }
}

// ---------------------------------------------------------------------------
// fp16 GEMM (R8 geometry): C = A @ W^T + bias.
// TERMS=3: AhWh + AhWl + AlWh (Q,K proj).  TERMS=1: AhWh only (V, O proj).
// CTA 128x128, 8 warps (32x64), Kc=32, 3-stage cp.async, 2 CTAs/SM.
// Loader: 256 threads, srow=tid>>1 (0..127), shalf=tid&1 — one 32B row-half
// per thread per tile (validated R8/R9 mapping; R12's bug was row=tid 0..255).
// ---------------------------------------------------------------------------
#define GTILE_B   8192             // 128 rows * 64 B
#define GBUF_B    (4*GTILE_B)      // 32768 (Ah,Al,Wh,Wl slots)
#define GEMM_SMEM (3*GBUF_B)       // 98304; x2 CTAs = 196608

__device__ __forceinline__ uint32_t gswz(int row, int c16) {
    return (uint32_t)row*64 + (uint32_t)((c16 ^ ((row >> 1) & 3)) * 16);
}

template<int TERMS>
__device__ __forceinline__ void gemm_fill(
    const __half* const* srcs, uint32_t stage_base, int kc, int srow, int shalf)
{
    const size_t g = (size_t)srow*D_MODEL + kc + shalf*16;
    const uint32_t s0 = stage_base + gswz(srow, shalf*2);
    const uint32_t s1 = stage_base + gswz(srow, shalf*2 + 1);
    #pragma unroll
    for (int t = 0; t < 4; t++) {
        if (TERMS == 1 && (t & 1)) continue;   // skip Al, Wl slots
        cp16(s0 + t*GTILE_B, srcs[t] + g);
        cp16(s1 + t*GTILE_B, srcs[t] + g + 8);
    }
}

template<int TERMS>
__device__ __forceinline__ void gemm_body(
    const __half* Ah, const __half* Al,
    const __half* Wh, const __half* Wl,
    const float* __restrict__ bias,
    float* __restrict__ outp, int dst, int bm, int bn, char* smem)
{
    const uint32_t sm0 = smem_to_u32(smem);
    const int tid  = threadIdx.x;
    const int lane = tid & 31;
    const int wid  = tid >> 5;
    const int wm = wid & 3;
    const int wn = wid >> 2;

    const __half* srcs[4] = {
        Ah + (size_t)bm*128*D_MODEL,
        Al + (size_t)bm*128*D_MODEL,
        Wh + (size_t)bn*128*D_MODEL,
        Wl + (size_t)bn*128*D_MODEL };

    const int srow  = tid >> 1;
    const int shalf = tid & 1;

    gemm_fill<TERMS>(srcs, sm0 + 0*GBUF_B, 0,  srow, shalf);
    cp_commit();
    gemm_fill<TERMS>(srcs, sm0 + 1*GBUF_B, 32, srow, shalf);
    cp_commit();

    const int a_row0 = wm*32 + (lane & 15);
    const int b_row0 = wn*64 + ((lane >> 4) & 1)*8 + (lane & 7);
    const int a_c16h = (lane >> 4) & 1;
    const int b_c16h = (lane >> 3) & 1;

    float acc[2][8][4] = {};

    for (int c = 0; c < 32; c++) {
        cp_wait<1>();
        __syncthreads();

        if (c < 30)
            gemm_fill<TERMS>(srcs, sm0 + ((c + 2) % 3)*GBUF_B, (c + 2)*32, srow, shalf);
        cp_commit();

        const uint32_t base = sm0 + (c % 3)*GBUF_B;
        #pragma unroll
        for (int ks = 0; ks < 2; ks++) {
            uint32_t ah[2][4], al[2][4];
            #pragma unroll
            for (int fm = 0; fm < 2; fm++) {
                const uint32_t ao = gswz(a_row0 + fm*16, ks*2 + a_c16h);
                ldsm_x4(ah[fm], base + 0*GTILE_B + ao);
                if (TERMS == 3) ldsm_x4(al[fm], base + 1*GTILE_B + ao);
            }
            #pragma unroll
            for (int p = 0; p < 4; p++) {
                const uint32_t bo = gswz(b_row0 + p*16, ks*2 + b_c16h);
                uint32_t bh[4], bl[4];
                ldsm_x4(bh, base + 2*GTILE_B + bo);
                if (TERMS == 3) ldsm_x4(bl, base + 3*GTILE_B + bo);
                #pragma unroll
                for (int q = 0; q < 2; q++) {
                    const int fn = p*2 + q;
                    #pragma unroll
                    for (int fm = 0; fm < 2; fm++) {
                        mma16816f(acc[fm][fn], ah[fm], bh + q*2);
                        if (TERMS == 3) {
                            mma16816f(acc[fm][fn], ah[fm], bl + q*2);
                            mma16816f(acc[fm][fn], al[fm], bh + q*2);
                        }
                    }
                }
            }
        }
    }

    // Epilogue
    const int r4 = lane >> 2;
    const int kw = lane & 3;
    #pragma unroll
    for (int fm = 0; fm < 2; fm++) {
        #pragma unroll
        for (int fn = 0; fn < 8; fn++) {
            const int row = bm*128 + wm*32 + fm*16 + r4;
            const int col = bn*128 + wn*64 + fn*8 + kw*2;
            const float b0 = bias[col], b1 = bias[col+1];
            #pragma unroll
            for (int p = 0; p < 2; p++) {
                const int rr = row + p*8;
                const float vx = acc[fm][fn][p*2+0] + b0;
                const float vy = acc[fm][fn][p*2+1] + b1;
                if (dst < 3) {
                    const int b = rr >> 11, s = rr & 2047;
                    const int h = col >> 6, d = col & 63;
                    const size_t idx = (((size_t)(b*HEADS + h))*SEQ + s)*DKH + d;
                    uint32_t hi, lo;
                    pack_hl(vx, vy, hi, lo);              // bf16 pair for flash
                    *(uint32_t*)(g_qkvh[dst] + idx) = hi;
                    *(uint32_t*)(g_qkvl[dst] + idx) = lo;
                } else {
                    float2 ov; ov.x = vx; ov.y = vy;
                    *(float2*)(outp + (size_t)rr*D_MODEL + col) = ov;
                }
            }
        }
    }
}

// Q,K projections: 3-term.  z = blockIdx.z in {0,1}.
__global__ __launch_bounds__(256, 2) void gemm_qk(
    const float* __restrict__ bq, const float* __restrict__ bk)
{
    extern __shared__ char smem[];
    const int z = blockIdx.z;
    const float* bias = (z == 0) ? bq : bk;
    gemm_body<3>(g_xh[z], g_xl[z], g_wh[z], g_wl[z], bias,
                 nullptr, z, blockIdx.y, blockIdx.x, smem);
}

// V projection: single-term fp16 (rel err ~2e-4, linear path).
__global__ __launch_bounds__(256, 2) void gemm_v(const float* __restrict__ bv)
{
    extern __shared__ char smem[];
    gemm_body<1>(g_xh[2], g_xh[2], g_wh[2], g_wh[2], bv,
                 nullptr, 2, blockIdx.y, blockIdx.x, smem);
}

// Output projection: single-term fp16.
__global__ __launch_bounds__(256, 2) void gemm_out(
    const float* __restrict__ bo, float* __restrict__ outp)
{
    extern __shared__ char smem[];
    gemm_body<1>(g_aoh, g_aoh, g_wh[3], g_wh[3], bo,
                 outp, 3, blockIdx.y, blockIdx.x, smem);
}

// ---------------------------------------------------------------------------
// Tensor-core flash attention — proven R8/R11 version; epilogue writes
// single fp16 O (error 1.4e-4, within budget).
// ---------------------------------------------------------------------------
#define KVTILE_B   8192                // 64 rows * 128 B
#define KVBUF_B    (4*KVTILE_B)        // 32768
#define FLASH_SMEM (3*KVBUF_B)         // 98304; x2 CTAs = 196608

__device__ __forceinline__ uint32_t fswz(int row, int c16) {
    return (uint32_t)row*128 + (uint32_t)((c16 ^ (row & 7)) * 16);
}

__global__ __launch_bounds__(256, 2) void flash_mma(void)
{
    extern __shared__ char fsm[];
    const uint32_t sm0 = smem_to_u32(fsm);
    const int tid  = threadIdx.x;
    const int lane = tid & 31;
    const int wid  = tid >> 5;            // 0..7
    const int bh   = blockIdx.y;
    const int q0   = blockIdx.x * 128;
    const int b    = bh >> 4, h = bh & 15;

    const __nv_bfloat16* Qh = g_qkvh[0] + ((size_t)bh*SEQ + q0 + wid*16)*DKH;
    const __nv_bfloat16* Ql = g_qkvl[0] + ((size_t)bh*SEQ + q0 + wid*16)*DKH;
    const __nv_bfloat16* Kh = g_qkvh[1] + (size_t)bh*SEQ*DKH;
    const __nv_bfloat16* Kl = g_qkvl[1] + (size_t)bh*SEQ*DKH;
    const __nv_bfloat16* Vh = g_qkvh[2] + (size_t)bh*SEQ*DKH;
    const __nv_bfloat16* Vl = g_qkvl[2] + (size_t)bh*SEQ*DKH;

    const int r4 = lane >> 2;
    const int kw = lane & 3;

    uint32_t qh[4][4], ql[4][4];
    #pragma unroll
    for (int ks = 0; ks < 4; ks++) {
        const int cb = ks*16 + kw*2;
        qh[ks][0] = *(const uint32_t*)(Qh + (size_t)r4*DKH + cb);
        qh[ks][1] = *(const uint32_t*)(Qh + (size_t)(r4+8)*DKH + cb);
        qh[ks][2] = *(const uint32_t*)(Qh + (size_t)r4*DKH + cb + 8);
        qh[ks][3] = *(const uint32_t*)(Qh + (size_t)(r4+8)*DKH + cb + 8);
        ql[ks][0] = *(const uint32_t*)(Ql + (size_t)r4*DKH + cb);
        ql[ks][1] = *(const uint32_t*)(Ql + (size_t)(r4+8)*DKH + cb);
        ql[ks][2] = *(const uint32_t*)(Ql + (size_t)r4*DKH + cb + 8);
        ql[ks][3] = *(const uint32_t*)(Ql + (size_t)(r4+8)*DKH + cb + 8);
    }

    const int  krow = tid >> 2;
    const int  kq   = tid & 3;
    const size_t gkoff = (size_t)krow*DKH + kq*16;
    const uint32_t s0off = fswz(krow, kq*2);
    const uint32_t s1off = fswz(krow, kq*2 + 1);
    const __nv_bfloat16* gsrc[4] = { Kh, Kl, Vh, Vl };

    const int k_row0 = ((lane >> 4) & 1)*8 + (lane & 7);
    const int k_c16h = (lane >> 3) & 1;
    const int v_row0 = ((lane >> 3) & 1)*8 + (lane & 7);
    const int v_c16h = (lane >> 4) & 1;

    float accO[8][4] = {};
    float lsum0 = 0.f, lsum1 = 0.f;

    #pragma unroll
    for (int ktp = 0; ktp < 2; ktp++) {
        const size_t g = (size_t)ktp*64*DKH + gkoff;
        const uint32_t sb = sm0 + ktp*KVBUF_B;
        #pragma unroll
        for (int t = 0; t < 4; t++) {
            cp16(sb + t*KVTILE_B + s0off, gsrc[t] + g);
            cp16(sb + t*KVTILE_B + s1off, gsrc[t] + g + 8);
        }
        cp_commit();
    }

    #pragma unroll 1
    for (int kt = 0; kt < SEQ/64; kt++) {
        cp_wait<1>();
        __syncthreads();

        if (kt < SEQ/64 - 2) {
            const size_t g = (size_t)(kt+2)*64*DKH + gkoff;
            const uint32_t sb = sm0 + ((kt+2) % 3)*KVBUF_B;
            #pragma unroll
            for (int t = 0; t < 4; t++) {
                cp16(sb + t*KVTILE_B + s0off, gsrc[t] + g);
                cp16(sb + t*KVTILE_B + s1off, gsrc[t] + g + 8);
            }
        }
        cp_commit();

        const uint32_t base = sm0 + (kt % 3)*KVBUF_B;

        float s[8][4] = {};
        #pragma unroll
        for (int ks = 0; ks < 4; ks++) {
            #pragma unroll
            for (int pp = 0; pp < 4; pp += 2) {
                uint32_t bhr[2][4], blr[2][4];
                #pragma unroll
                for (int pi = 0; pi < 2; pi++) {
                    const uint32_t bo = fswz((pp + pi)*16 + k_row0, ks*2 + k_c16h);
                    ldsm_x4(bhr[pi], base + 0*KVTILE_B + bo);
                    ldsm_x4(blr[pi], base + 1*KVTILE_B + bo);
                }
                #pragma unroll
                for (int t = 0; t < 3; t++) {
                    const uint32_t* aa = (t == 2) ? ql[ks] : qh[ks];
                    #pragma unroll
                    for (int pi = 0; pi < 2; pi++) {
                        #pragma unroll
                        for (int q = 0; q < 2; q++) {
                            const uint32_t* bb = (t == 1) ? (blr[pi] + q*2)
                                                          : (bhr[pi] + q*2);
                            mma16816(s[(pp + pi)*2 + q], aa, bb);
                        }
                    }
                }
            }
        }

        #pragma unroll
        for (int f = 0; f < 8; f++) {
            s[f][0] = __expf(s[f][0]);
            s[f][1] = __expf(s[f][1]);
            s[f][2] = __expf(s[f][2]);
            s[f][3] = __expf(s[f][3]);
            lsum0 += s[f][0] + s[f][1];
            lsum1 += s[f][2] + s[f][3];
        }

        #pragma unroll
        for (int ks = 0; ks < 4; ks++) {
            uint32_t pah[4], pal[4];
            const int f0 = 2*ks, f1 = 2*ks + 1;
            pack_hl(s[f0][0], s[f0][1], pah[0], pal[0]);
            pack_hl(s[f0][2], s[f0][3], pah[1], pal[1]);
            pack_hl(s[f1][0], s[f1][1], pah[2], pal[2]);
            pack_hl(s[f1][2], s[f1][3], pah[3], pal[3]);
            #pragma unroll
            for (int pp = 0; pp < 4; pp += 2) {
                uint32_t vhr[2][4], vlr[2][4];
                #pragma unroll
                for (int pi = 0; pi < 2; pi++) {
                    const uint32_t vo = fswz(ks*16 + v_row0, (pp + pi)*2 + v_c16h);
                    ldsm_x4_t(vhr[pi], base + 2*KVTILE_B + vo);
                    ldsm_x4_t(vlr[pi], base + 3*KVTILE_B + vo);
                }
                #pragma unroll
                for (int t = 0; t < 3; t++) {
                    const uint32_t* aa = (t == 2) ? pal : pah;
                    #pragma unroll
                    for (int pi = 0; pi < 2; pi++) {
                        #pragma unroll
                        for (int q = 0; q < 2; q++) {
                            const uint32_t* bb = (t == 1) ? (vlr[pi] + q*2)
                                                          : (vhr[pi] + q*2);
                            mma16816(accO[(pp + pi)*2 + q], aa, bb);
                        }
                    }
                }
            }
        }
    }

    lsum0 += __shfl_xor_sync(0xffffffffu, lsum0, 1);
    lsum0 += __shfl_xor_sync(0xffffffffu, lsum0, 2);
    lsum1 += __shfl_xor_sync(0xffffffffu, lsum1, 1);
    lsum1 += __shfl_xor_sync(0xffffffffu, lsum1, 2);
    const float inv0 = 1.f / lsum0;
    const float inv1 = 1.f / lsum1;

    const size_t obase = ((size_t)b*SEQ + q0 + wid*16)*D_MODEL + h*DKH;
    #pragma unroll
    for (int f = 0; f < 8; f++) {
        const int d = f*8 + kw*2;
        __half2 h0 = __floats2half2_rn(accO[f][0]*inv0, accO[f][1]*inv0);
        __half2 h1 = __floats2half2_rn(accO[f][2]*inv1, accO[f][3]*inv1);
        *(__half2*)(g_aoh + obase + (size_t)r4*D_MODEL + d)     = h0;
        *(__half2*)(g_aoh + obase + (size_t)(r4+8)*D_MODEL + d) = h1;
    }
}

// ---------------------------------------------------------------------------
// Launch
// ---------------------------------------------------------------------------
extern "C" void kernel_launch(void* const* d_in, const int* in_sizes, int n_in,
                              void* d_out, int out_size)
{
    const float* q  = (const float*)d_in[0];
    const float* k  = (const float*)d_in[1];
    const float* v  = (const float*)d_in[2];
    const float* Wq = (const float*)d_in[3];
    const float* bq = (const float*)d_in[4];
    const float* Wk = (const float*)d_in[5];
    const float* bk = (const float*)d_in[6];
    const float* Wv = (const float*)d_in[7];
    const float* bv = (const float*)d_in[8];
    const float* Wo = (const float*)d_in[9];
    const float* bo = (const float*)d_in[10];
    float* out = (float*)d_out;

    cudaFuncSetAttribute(gemm_qk,   cudaFuncAttributeMaxDynamicSharedMemorySize, GEMM_SMEM);
    cudaFuncSetAttribute(gemm_v,    cudaFuncAttributeMaxDynamicSharedMemorySize, GEMM_SMEM);
    cudaFuncSetAttribute(gemm_out,  cudaFuncAttributeMaxDynamicSharedMemorySize, GEMM_SMEM);
    cudaFuncSetAttribute(flash_mma, cudaFuncAttributeMaxDynamicSharedMemorySize, FLASH_SMEM);

    splitk_all<<<8192, 256>>>(q, k, v, Wq, Wk, Wv, Wo);

    dim3 gg(D_MODEL/128, MROWS/128);   // (8, 32)
    gemm_qk<<<dim3(8, 32, 2), 256, GEMM_SMEM>>>(bq, bk);
    gemm_v<<<gg, 256, GEMM_SMEM>>>(bv);

    flash_mma<<<dim3(SEQ/128, BATCH*HEADS), 256, FLASH_SMEM>>>();

    gemm_out<<<gg, 256, GEMM_SMEM>>>(bo, out);
}

// round 14
// speedup vs baseline: 1.6309x; 1.1525x over previous
#include <cuda_runtime.h>
#include <cuda_bf16.h>
#include <cuda_fp16.h>
#include <cstdint>

// Problem constants
#define D_MODEL 1024
#define SEQ     2048
#define BATCH   2
#define HEADS   16
#define DKH     64
#define MROWS   (BATCH*SEQ)          // 4096
#define NX      (MROWS*D_MODEL)      // 2^22
#define NW      (D_MODEL*D_MODEL)    // 2^20

// ---------------------------------------------------------------------------
// Scratch (device globals — no allocation allowed)
// ---------------------------------------------------------------------------
__device__ __half g_xh[3][NX];                    // q,k,v inputs fp16 hi
__device__ __half g_xl[3][NX];                    // fp16 lo (lo unused for v)
__device__ __half g_wh[4][NW];
__device__ __half g_wl[4][NW];                    // lo unused for Wv, Wo
__device__ __nv_bfloat16 g_qkvh[2][BATCH*HEADS*SEQ*DKH];  // Q/K bf16 hi (flash)
__device__ __nv_bfloat16 g_qkvl[2][BATCH*HEADS*SEQ*DKH];  // Q/K bf16 lo
__device__ __half g_vh[BATCH*HEADS*SEQ*DKH];      // V fp16 single
__device__ __half g_aoh[NX];                      // attention out fp16 single

// ---------------------------------------------------------------------------
// PTX helpers
// ---------------------------------------------------------------------------
__device__ __forceinline__ uint32_t smem_to_u32(const void* p) {
    uint32_t a;
    asm("{ .reg .u64 t; cvta.to.shared.u64 t, %1; cvt.u32.u64 %0, t; }"
        : "=r"(a) : "l"(p));
    return a;
}

// bf16 MMA, f32 acc (flash QK^T)
__device__ __forceinline__ void mma16816(float* c, const uint32_t* a, const uint32_t* b)
{
    asm volatile(
        "mma.sync.aligned.m16n8k16.row.col.f32.bf16.bf16.f32 "
        "{%0,%1,%2,%3}, {%4,%5,%6,%7}, {%8,%9}, {%0,%1,%2,%3};"
        : "+f"(c[0]), "+f"(c[1]), "+f"(c[2]), "+f"(c[3])
        : "r"(a[0]), "r"(a[1]), "r"(a[2]), "r"(a[3]), "r"(b[0]), "r"(b[1]));
}

// fp16 MMA, f32 acc (projections + flash PV)
__device__ __forceinline__ void mma16816f(float* c, const uint32_t* a, const uint32_t* b)
{
    asm volatile(
        "mma.sync.aligned.m16n8k16.row.col.f32.f16.f16.f32 "
        "{%0,%1,%2,%3}, {%4,%5,%6,%7}, {%8,%9}, {%0,%1,%2,%3};"
        : "+f"(c[0]), "+f"(c[1]), "+f"(c[2]), "+f"(c[3])
        : "r"(a[0]), "r"(a[1]), "r"(a[2]), "r"(a[3]), "r"(b[0]), "r"(b[1]));
}

__device__ __forceinline__ void ldsm_x4(uint32_t* r, uint32_t addr)
{
    asm volatile("ldmatrix.sync.aligned.m8n8.x4.shared.b16 {%0,%1,%2,%3}, [%4];"
        : "=r"(r[0]), "=r"(r[1]), "=r"(r[2]), "=r"(r[3]) : "r"(addr));
}

__device__ __forceinline__ void ldsm_x4_t(uint32_t* r, uint32_t addr)
{
    asm volatile("ldmatrix.sync.aligned.m8n8.x4.trans.shared.b16 {%0,%1,%2,%3}, [%4];"
        : "=r"(r[0]), "=r"(r[1]), "=r"(r[2]), "=r"(r[3]) : "r"(addr));
}

__device__ __forceinline__ void cp16(uint32_t saddr, const void* g) {
    asm volatile("cp.async.cg.shared.global [%0], [%1], 16;" :: "r"(saddr), "l"(g));
}
__device__ __forceinline__ void cp_commit() {
    asm volatile("cp.async.commit_group;");
}
template<int N> __device__ __forceinline__ void cp_wait() {
    asm volatile("cp.async.wait_group %0;" :: "n"(N));
}

// fp32 pair -> bf16x2 hi + lo
__device__ __forceinline__ void pack_hl(float a, float b, uint32_t& hi, uint32_t& lo)
{
    __nv_bfloat162 h = __floats2bfloat162_rn(a, b);
    float ra = a - __bfloat162float(h.x);
    float rb = b - __bfloat162float(h.y);
    __nv_bfloat162 l = __floats2bfloat162_rn(ra, rb);
    hi = *reinterpret_cast<uint32_t*>(&h);
    lo = *reinterpret_cast<uint32_t*>(&l);
}

// fp32 pair -> fp16x2 hi + lo
__device__ __forceinline__ void pack_hl16(float a, float b, uint32_t& hi, uint32_t& lo)
{
    __half2 h = __floats2half2_rn(a, b);
    float ra = a - __half2float(__low2half(h));
    float rb = b - __half2float(__high2half(h));
    __half2 l = __floats2half2_rn(ra, rb);
    hi = *reinterpret_cast<uint32_t*>(&h);
    lo = *reinterpret_cast<uint32_t*>(&l);
}

// fp32 pair -> fp16x2 single
__device__ __forceinline__ uint32_t pack16(float a, float b)
{
    __half2 h = __floats2half2_rn(a, b);
    return *reinterpret_cast<uint32_t*>(&h);
}

// ---------------------------------------------------------------------------
// Fused fp32 -> fp16 (hi, lo) split: all 7 tensors in one launch.
// ---------------------------------------------------------------------------
__global__ __launch_bounds__(256) void splitk_all(
    const float* __restrict__ q,  const float* __restrict__ k,
    const float* __restrict__ v,  const float* __restrict__ Wq,
    const float* __restrict__ Wk, const float* __restrict__ Wv,
    const float* __restrict__ Wo)
{
    const size_t total4 = (size_t)(3*NX + 4*NW) / 4;
    for (size_t ch = (size_t)blockIdx.x*blockDim.x + threadIdx.x; ch < total4;
         ch += (size_t)gridDim.x*blockDim.x) {
        const size_t i = ch*4;
        const float* src;
        __half *hi, *lo;
        size_t off;
        if (i < (size_t)3*NX) {
            const int w = (int)(i >> 22);
            off = i & (NX - 1);
            src = (w == 0) ? q : (w == 1) ? k : v;
            hi = g_xh[w]; lo = g_xl[w];
        } else {
            const size_t j = i - (size_t)3*NX;
            const int w = (int)(j >> 20);
            off = j & (NW - 1);
            src = (w == 0) ? Wq : (w == 1) ? Wk : (w == 2) ? Wv : Wo;
            hi = g_wh[w]; lo = g_wl[w];
        }
        float4 vv = *(const float4*)(src + off);
        uint32_t h0, l0, h1, l1;
        pack_hl16(vv.x, vv.y, h0, l0);
        pack_hl16(vv.z, vv.w, h1, l1);
        *(uint32_t*)(hi + off)     = h0;
        *(uint32_t*)(hi + off + 2) = h1;
        *(uint32_t*)(lo + off)     = l0;
        *(uint32_t*)(lo + off + 2) = l1;
    }
}

// ---------------------------------------------------------------------------
// fp16 GEMM: C = A @ W^T + bias.  TERMS=3 (Q,K) or 1 (V, O).
// dst 0/1: bf16 hi/lo -> g_qkvh/l[dst]; dst 2: fp16 -> g_vh; dst 3: fp32 out.
// CTA 128x128, 8 warps (32x64), Kc=32, 3-stage cp.async, 2 CTAs/SM.
// ---------------------------------------------------------------------------
#define GTILE_B   8192             // 128 rows * 64 B
#define GBUF_B    (4*GTILE_B)      // 32768 (Ah,Al,Wh,Wl slots)
#define GEMM_SMEM (3*GBUF_B)       // 98304; x2 CTAs = 196608

__device__ __forceinline__ uint32_t gswz(int row, int c16) {
    return (uint32_t)row*64 + (uint32_t)((c16 ^ ((row >> 1) & 3)) * 16);
}

template<int TERMS>
__device__ __forceinline__ void gemm_fill(
    const __half* const* srcs, uint32_t stage_base, int kc, int srow, int shalf)
{
    const size_t g = (size_t)srow*D_MODEL + kc + shalf*16;
    const uint32_t s0 = stage_base + gswz(srow, shalf*2);
    const uint32_t s1 = stage_base + gswz(srow, shalf*2 + 1);
    #pragma unroll
    for (int t = 0; t < 4; t++) {
        if (TERMS == 1 && (t & 1)) continue;   // skip Al, Wl slots
        cp16(s0 + t*GTILE_B, srcs[t] + g);
        cp16(s1 + t*GTILE_B, srcs[t] + g + 8);
    }
}

template<int TERMS>
__device__ __forceinline__ void gemm_body(
    const __half* Ah, const __half* Al,
    const __half* Wh, const __half* Wl,
    const float* __restrict__ bias,
    float* __restrict__ outp, int dst, int bm, int bn, char* smem)
{
    const uint32_t sm0 = smem_to_u32(smem);
    const int tid  = threadIdx.x;
    const int lane = tid & 31;
    const int wid  = tid >> 5;
    const int wm = wid & 3;
    const int wn = wid >> 2;

    const __half* srcs[4] = {
        Ah + (size_t)bm*128*D_MODEL,
        Al + (size_t)bm*128*D_MODEL,
        Wh + (size_t)bn*128*D_MODEL,
        Wl + (size_t)bn*128*D_MODEL };

    const int srow  = tid >> 1;
    const int shalf = tid & 1;

    gemm_fill<TERMS>(srcs, sm0 + 0*GBUF_B, 0,  srow, shalf);
    cp_commit();
    gemm_fill<TERMS>(srcs, sm0 + 1*GBUF_B, 32, srow, shalf);
    cp_commit();

    const int a_row0 = wm*32 + (lane & 15);
    const int b_row0 = wn*64 + ((lane >> 4) & 1)*8 + (lane & 7);
    const int a_c16h = (lane >> 4) & 1;
    const int b_c16h = (lane >> 3) & 1;

    float acc[2][8][4] = {};

    for (int c = 0; c < 32; c++) {
        cp_wait<1>();
        __syncthreads();

        if (c < 30)
            gemm_fill<TERMS>(srcs, sm0 + ((c + 2) % 3)*GBUF_B, (c + 2)*32, srow, shalf);
        cp_commit();

        const uint32_t base = sm0 + (c % 3)*GBUF_B;
        #pragma unroll
        for (int ks = 0; ks < 2; ks++) {
            uint32_t ah[2][4], al[2][4];
            #pragma unroll
            for (int fm = 0; fm < 2; fm++) {
                const uint32_t ao = gswz(a_row0 + fm*16, ks*2 + a_c16h);
                ldsm_x4(ah[fm], base + 0*GTILE_B + ao);
                if (TERMS == 3) ldsm_x4(al[fm], base + 1*GTILE_B + ao);
            }
            #pragma unroll
            for (int p = 0; p < 4; p++) {
                const uint32_t bo = gswz(b_row0 + p*16, ks*2 + b_c16h);
                uint32_t bh[4], bl[4];
                ldsm_x4(bh, base + 2*GTILE_B + bo);
                if (TERMS == 3) ldsm_x4(bl, base + 3*GTILE_B + bo);
                #pragma unroll
                for (int q = 0; q < 2; q++) {
                    const int fn = p*2 + q;
                    #pragma unroll
                    for (int fm = 0; fm < 2; fm++) {
                        mma16816f(acc[fm][fn], ah[fm], bh + q*2);
                        if (TERMS == 3) {
                            mma16816f(acc[fm][fn], ah[fm], bl + q*2);
                            mma16816f(acc[fm][fn], al[fm], bh + q*2);
                        }
                    }
                }
            }
        }
    }

    // Epilogue
    const int r4 = lane >> 2;
    const int kw = lane & 3;
    #pragma unroll
    for (int fm = 0; fm < 2; fm++) {
        #pragma unroll
        for (int fn = 0; fn < 8; fn++) {
            const int row = bm*128 + wm*32 + fm*16 + r4;
            const int col = bn*128 + wn*64 + fn*8 + kw*2;
            const float b0 = bias[col], b1 = bias[col+1];
            #pragma unroll
            for (int p = 0; p < 2; p++) {
                const int rr = row + p*8;
                const float vx = acc[fm][fn][p*2+0] + b0;
                const float vy = acc[fm][fn][p*2+1] + b1;
                if (dst < 2) {
                    const int b = rr >> 11, s = rr & 2047;
                    const int h = col >> 6, d = col & 63;
                    const size_t idx = (((size_t)(b*HEADS + h))*SEQ + s)*DKH + d;
                    uint32_t hi, lo;
                    pack_hl(vx, vy, hi, lo);              // bf16 pair for flash QK
                    *(uint32_t*)(g_qkvh[dst] + idx) = hi;
                    *(uint32_t*)(g_qkvl[dst] + idx) = lo;
                } else if (dst == 2) {
                    const int b = rr >> 11, s = rr & 2047;
                    const int h = col >> 6, d = col & 63;
                    const size_t idx = (((size_t)(b*HEADS + h))*SEQ + s)*DKH + d;
                    *(uint32_t*)(g_vh + idx) = pack16(vx, vy);   // V fp16 single
                } else {
                    float2 ov; ov.x = vx; ov.y = vy;
                    *(float2*)(outp + (size_t)rr*D_MODEL + col) = ov;
                }
            }
        }
    }
}

// Q,K projections: 3-term.  z = blockIdx.z in {0,1}.
__global__ __launch_bounds__(256, 2) void gemm_qk(
    const float* __restrict__ bq, const float* __restrict__ bk)
{
    extern __shared__ char smem[];
    const int z = blockIdx.z;
    const float* bias = (z == 0) ? bq : bk;
    gemm_body<3>(g_xh[z], g_xl[z], g_wh[z], g_wl[z], bias,
                 nullptr, z, blockIdx.y, blockIdx.x, smem);
}

// V projection: single-term fp16, writes fp16 V for flash.
__global__ __launch_bounds__(256, 2) void gemm_v(const float* __restrict__ bv)
{
    extern __shared__ char smem[];
    gemm_body<1>(g_xh[2], g_xh[2], g_wh[2], g_wh[2], bv,
                 nullptr, 2, blockIdx.y, blockIdx.x, smem);
}

// Output projection: single-term fp16.
__global__ __launch_bounds__(256, 2) void gemm_out(
    const float* __restrict__ bo, float* __restrict__ outp)
{
    extern __shared__ char smem[];
    gemm_body<1>(g_aoh, g_aoh, g_wh[3], g_wh[3], bo,
                 outp, 3, blockIdx.y, blockIdx.x, smem);
}

// ---------------------------------------------------------------------------
// Flash attention: QK^T 3-term bf16; ONLINE SOFTMAX (running row max) so
// P fits fp16 -> PV single-term fp16.  128 MMAs/tile/warp (was 192).
// KV smem: Khi, Klo (bf16), V (fp16) — 3 x 8KB per stage, 3 stages.
// ---------------------------------------------------------------------------
#define KVTILE_B   8192                // 64 rows * 128 B
#define KVBUF_B    (3*KVTILE_B)        // 24576 (Khi, Klo, V)
#define FLASH_SMEM (3*KVBUF_B)         // 73728; x2 CTAs = 147456

__device__ __forceinline__ uint32_t fswz(int row, int c16) {
    return (uint32_t)row*128 + (uint32_t)((c16 ^ (row & 7)) * 16);
}

__global__ __launch_bounds__(256, 2) void flash_mma(void)
{
    extern __shared__ char fsm[];
    const uint32_t sm0 = smem_to_u32(fsm);
    const int tid  = threadIdx.x;
    const int lane = tid & 31;
    const int wid  = tid >> 5;            // 0..7
    const int bh   = blockIdx.y;
    const int q0   = blockIdx.x * 128;
    const int b    = bh >> 4, h = bh & 15;

    const __nv_bfloat16* Qh = g_qkvh[0] + ((size_t)bh*SEQ + q0 + wid*16)*DKH;
    const __nv_bfloat16* Ql = g_qkvl[0] + ((size_t)bh*SEQ + q0 + wid*16)*DKH;
    const __nv_bfloat16* Kh = g_qkvh[1] + (size_t)bh*SEQ*DKH;
    const __nv_bfloat16* Kl = g_qkvl[1] + (size_t)bh*SEQ*DKH;
    const __half*        Vp = g_vh      + (size_t)bh*SEQ*DKH;

    const int r4 = lane >> 2;
    const int kw = lane & 3;

    uint32_t qh[4][4], ql[4][4];
    #pragma unroll
    for (int ks = 0; ks < 4; ks++) {
        const int cb = ks*16 + kw*2;
        qh[ks][0] = *(const uint32_t*)(Qh + (size_t)r4*DKH + cb);
        qh[ks][1] = *(const uint32_t*)(Qh + (size_t)(r4+8)*DKH + cb);
        qh[ks][2] = *(const uint32_t*)(Qh + (size_t)r4*DKH + cb + 8);
        qh[ks][3] = *(const uint32_t*)(Qh + (size_t)(r4+8)*DKH + cb + 8);
        ql[ks][0] = *(const uint32_t*)(Ql + (size_t)r4*DKH + cb);
        ql[ks][1] = *(const uint32_t*)(Ql + (size_t)(r4+8)*DKH + cb);
        ql[ks][2] = *(const uint32_t*)(Ql + (size_t)r4*DKH + cb + 8);
        ql[ks][3] = *(const uint32_t*)(Ql + (size_t)(r4+8)*DKH + cb + 8);
    }

    const int  krow = tid >> 2;
    const int  kq   = tid & 3;
    const size_t gkoff = (size_t)krow*DKH + kq*16;
    const uint32_t s0off = fswz(krow, kq*2);
    const uint32_t s1off = fswz(krow, kq*2 + 1);

    const int k_row0 = ((lane >> 4) & 1)*8 + (lane & 7);
    const int k_c16h = (lane >> 3) & 1;
    const int v_row0 = ((lane >> 3) & 1)*8 + (lane & 7);
    const int v_c16h = (lane >> 4) & 1;

    float accO[8][4] = {};
    float lsum0 = 0.f, lsum1 = 0.f;
    float m0 = -1e30f, m1 = -1e30f;

    #pragma unroll
    for (int ktp = 0; ktp < 2; ktp++) {
        const size_t g = (size_t)ktp*64*DKH + gkoff;
        const uint32_t sb = sm0 + ktp*KVBUF_B;
        cp16(sb + 0*KVTILE_B + s0off, Kh + g);
        cp16(sb + 0*KVTILE_B + s1off, Kh + g + 8);
        cp16(sb + 1*KVTILE_B + s0off, Kl + g);
        cp16(sb + 1*KVTILE_B + s1off, Kl + g + 8);
        cp16(sb + 2*KVTILE_B + s0off, Vp + g);
        cp16(sb + 2*KVTILE_B + s1off, Vp + g + 8);
        cp_commit();
    }

    #pragma unroll 1
    for (int kt = 0; kt < SEQ/64; kt++) {
        cp_wait<1>();
        __syncthreads();

        if (kt < SEQ/64 - 2) {
            const size_t g = (size_t)(kt+2)*64*DKH + gkoff;
            const uint32_t sb = sm0 + ((kt+2) % 3)*KVBUF_B;
            cp16(sb + 0*KVTILE_B + s0off, Kh + g);
            cp16(sb + 0*KVTILE_B + s1off, Kh + g + 8);
            cp16(sb + 1*KVTILE_B + s0off, Kl + g);
            cp16(sb + 1*KVTILE_B + s1off, Kl + g + 8);
            cp16(sb + 2*KVTILE_B + s0off, Vp + g);
            cp16(sb + 2*KVTILE_B + s1off, Vp + g + 8);
        }
        cp_commit();

        const uint32_t base = sm0 + (kt % 3)*KVBUF_B;

        // ---- scores: S = Q K^T (3-term bf16) ----
        float s[8][4] = {};
        #pragma unroll
        for (int ks = 0; ks < 4; ks++) {
            #pragma unroll
            for (int pp = 0; pp < 4; pp += 2) {
                uint32_t bhr[2][4], blr[2][4];
                #pragma unroll
                for (int pi = 0; pi < 2; pi++) {
                    const uint32_t bo = fswz((pp + pi)*16 + k_row0, ks*2 + k_c16h);
                    ldsm_x4(bhr[pi], base + 0*KVTILE_B + bo);
                    ldsm_x4(blr[pi], base + 1*KVTILE_B + bo);
                }
                #pragma unroll
                for (int t = 0; t < 3; t++) {
                    const uint32_t* aa = (t == 2) ? ql[ks] : qh[ks];
                    #pragma unroll
                    for (int pi = 0; pi < 2; pi++) {
                        #pragma unroll
                        for (int q = 0; q < 2; q++) {
                            const uint32_t* bb = (t == 1) ? (blr[pi] + q*2)
                                                          : (bhr[pi] + q*2);
                            mma16816(s[(pp + pi)*2 + q], aa, bb);
                        }
                    }
                }
            }
        }

        // ---- online softmax: running row max + rescale ----
        float tm0 = s[0][0], tm1 = s[0][2];
        #pragma unroll
        for (int f = 0; f < 8; f++) {
            tm0 = fmaxf(tm0, fmaxf(s[f][0], s[f][1]));
            tm1 = fmaxf(tm1, fmaxf(s[f][2], s[f][3]));
        }
        tm0 = fmaxf(tm0, __shfl_xor_sync(0xffffffffu, tm0, 1));
        tm0 = fmaxf(tm0, __shfl_xor_sync(0xffffffffu, tm0, 2));
        tm1 = fmaxf(tm1, __shfl_xor_sync(0xffffffffu, tm1, 1));
        tm1 = fmaxf(tm1, __shfl_xor_sync(0xffffffffu, tm1, 2));
        const float mn0 = fmaxf(m0, tm0);
        const float mn1 = fmaxf(m1, tm1);
        const float c0 = __expf(m0 - mn0);
        const float c1 = __expf(m1 - mn1);
        m0 = mn0; m1 = mn1;
        lsum0 *= c0; lsum1 *= c1;
        #pragma unroll
        for (int f = 0; f < 8; f++) {
            accO[f][0] *= c0; accO[f][1] *= c0;
            accO[f][2] *= c1; accO[f][3] *= c1;
        }

        #pragma unroll
        for (int f = 0; f < 8; f++) {
            s[f][0] = __expf(s[f][0] - mn0);
            s[f][1] = __expf(s[f][1] - mn0);
            s[f][2] = __expf(s[f][2] - mn1);
            s[f][3] = __expf(s[f][3] - mn1);
            lsum0 += s[f][0] + s[f][1];
            lsum1 += s[f][2] + s[f][3];
        }

        // ---- O += P V  (single-term fp16) ----
        #pragma unroll
        for (int ks = 0; ks < 4; ks++) {
            uint32_t pa[4];
            const int f0 = 2*ks, f1 = 2*ks + 1;
            pa[0] = pack16(s[f0][0], s[f0][1]);
            pa[1] = pack16(s[f0][2], s[f0][3]);
            pa[2] = pack16(s[f1][0], s[f1][1]);
            pa[3] = pack16(s[f1][2], s[f1][3]);
            #pragma unroll
            for (int p = 0; p < 4; p++) {
                const uint32_t vo = fswz(ks*16 + v_row0, p*2 + v_c16h);
                uint32_t vr[4];
                ldsm_x4_t(vr, base + 2*KVTILE_B + vo);
                mma16816f(accO[p*2 + 0], pa, vr + 0);
                mma16816f(accO[p*2 + 1], pa, vr + 2);
            }
        }
    }

    lsum0 += __shfl_xor_sync(0xffffffffu, lsum0, 1);
    lsum0 += __shfl_xor_sync(0xffffffffu, lsum0, 2);
    lsum1 += __shfl_xor_sync(0xffffffffu, lsum1, 1);
    lsum1 += __shfl_xor_sync(0xffffffffu, lsum1, 2);
    const float inv0 = 1.f / lsum0;
    const float inv1 = 1.f / lsum1;

    const size_t obase = ((size_t)b*SEQ + q0 + wid*16)*D_MODEL + h*DKH;
    #pragma unroll
    for (int f = 0; f < 8; f++) {
        const int d = f*8 + kw*2;
        *(uint32_t*)(g_aoh + obase + (size_t)r4*D_MODEL + d) =
            pack16(accO[f][0]*inv0, accO[f][1]*inv0);
        *(uint32_t*)(g_aoh + obase + (size_t)(r4+8)*D_MODEL + d) =
            pack16(accO[f][2]*inv1, accO[f][3]*inv1);
    }
}

// ---------------------------------------------------------------------------
// Launch
// ---------------------------------------------------------------------------
extern "C" void kernel_launch(void* const* d_in, const int* in_sizes, int n_in,
                              void* d_out, int out_size)
{
    const float* q  = (const float*)d_in[0];
    const float* k  = (const float*)d_in[1];
    const float* v  = (const float*)d_in[2];
    const float* Wq = (const float*)d_in[3];
    const float* bq = (const float*)d_in[4];
    const float* Wk = (const float*)d_in[5];
    const float* bk = (const float*)d_in[6];
    const float* Wv = (const float*)d_in[7];
    const float* bv = (const float*)d_in[8];
    const float* Wo = (const float*)d_in[9];
    const float* bo = (const float*)d_in[10];
    float* out = (float*)d_out;

    cudaFuncSetAttribute(gemm_qk,   cudaFuncAttributeMaxDynamicSharedMemorySize, GEMM_SMEM);
    cudaFuncSetAttribute(gemm_v,    cudaFuncAttributeMaxDynamicSharedMemorySize, GEMM_SMEM);
    cudaFuncSetAttribute(gemm_out,  cudaFuncAttributeMaxDynamicSharedMemorySize, GEMM_SMEM);
    cudaFuncSetAttribute(flash_mma, cudaFuncAttributeMaxDynamicSharedMemorySize, FLASH_SMEM);

    splitk_all<<<8192, 256>>>(q, k, v, Wq, Wk, Wv, Wo);

    dim3 gg(D_MODEL/128, MROWS/128);   // (8, 32)
    gemm_qk<<<dim3(8, 32, 2), 256, GEMM_SMEM>>>(bq, bk);
    gemm_v<<<gg, 256, GEMM_SMEM>>>(bv);

    flash_mma<<<dim3(SEQ/128, BATCH*HEADS), 256, FLASH_SMEM>>>();

    gemm_out<<<gg, 256, GEMM_SMEM>>>(bo, out);
}

// round 16
// speedup vs baseline: 1.7181x; 1.0535x over previous
#include <cuda_runtime.h>
#include <cuda_bf16.h>
#include <cuda_fp16.h>
#include <cstdint>

// Problem constants
#define D_MODEL 1024
#define SEQ     2048
#define BATCH   2
#define HEADS   16
#define DKH     64
#define MROWS   (BATCH*SEQ)          // 4096
#define NX      (MROWS*D_MODEL)      // 2^22
#define NW      (D_MODEL*D_MODEL)    // 2^20

// ---------------------------------------------------------------------------
// Scratch (device globals — no allocation allowed)
// ---------------------------------------------------------------------------
__device__ __half g_xh[3][NX];                    // q,k,v inputs fp16 hi
__device__ __half g_xl[3][NX];                    // fp16 lo (lo unused for v)
__device__ __half g_wh[4][NW];
__device__ __half g_wl[4][NW];                    // lo unused for Wv, Wo
__device__ __nv_bfloat16 g_qkvh[2][BATCH*HEADS*SEQ*DKH];  // Q/K bf16 hi (flash)
__device__ __nv_bfloat16 g_qkvl[2][BATCH*HEADS*SEQ*DKH];  // Q/K bf16 lo
__device__ __half g_vh[BATCH*HEADS*SEQ*DKH];      // V fp16 single
__device__ __half g_aoh[NX];                      // attention out fp16 single

// ---------------------------------------------------------------------------
// PTX helpers
// ---------------------------------------------------------------------------
__device__ __forceinline__ uint32_t smem_to_u32(const void* p) {
    uint32_t a;
    asm("{ .reg .u64 t; cvta.to.shared.u64 t, %1; cvt.u32.u64 %0, t; }"
        : "=r"(a) : "l"(p));
    return a;
}

__device__ __forceinline__ float ex2f(float x) {
    float r;
    asm("ex2.approx.f32 %0, %1;" : "=f"(r) : "f"(x));
    return r;
}

// bf16 MMA, f32 acc (flash QK^T)
__device__ __forceinline__ void mma16816(float* c, const uint32_t* a, const uint32_t* b)
{
    asm volatile(
        "mma.sync.aligned.m16n8k16.row.col.f32.bf16.bf16.f32 "
        "{%0,%1,%2,%3}, {%4,%5,%6,%7}, {%8,%9}, {%0,%1,%2,%3};"
        : "+f"(c[0]), "+f"(c[1]), "+f"(c[2]), "+f"(c[3])
        : "r"(a[0]), "r"(a[1]), "r"(a[2]), "r"(a[3]), "r"(b[0]), "r"(b[1]));
}

// fp16 MMA, f32 acc (projections + flash PV)
__device__ __forceinline__ void mma16816f(float* c, const uint32_t* a, const uint32_t* b)
{
    asm volatile(
        "mma.sync.aligned.m16n8k16.row.col.f32.f16.f16.f32 "
        "{%0,%1,%2,%3}, {%4,%5,%6,%7}, {%8,%9}, {%0,%1,%2,%3};"
        : "+f"(c[0]), "+f"(c[1]), "+f"(c[2]), "+f"(c[3])
        : "r"(a[0]), "r"(a[1]), "r"(a[2]), "r"(a[3]), "r"(b[0]), "r"(b[1]));
}

__device__ __forceinline__ void ldsm_x4(uint32_t* r, uint32_t addr)
{
    asm volatile("ldmatrix.sync.aligned.m8n8.x4.shared.b16 {%0,%1,%2,%3}, [%4];"
        : "=r"(r[0]), "=r"(r[1]), "=r"(r[2]), "=r"(r[3]) : "r"(addr));
}

__device__ __forceinline__ void ldsm_x4_t(uint32_t* r, uint32_t addr)
{
    asm volatile("ldmatrix.sync.aligned.m8n8.x4.trans.shared.b16 {%0,%1,%2,%3}, [%4];"
        : "=r"(r[0]), "=r"(r[1]), "=r"(r[2]), "=r"(r[3]) : "r"(addr));
}

__device__ __forceinline__ void cp16(uint32_t saddr, const void* g) {
    asm volatile("cp.async.cg.shared.global [%0], [%1], 16;" :: "r"(saddr), "l"(g));
}
__device__ __forceinline__ void cp_commit() {
    asm volatile("cp.async.commit_group;");
}
template<int N> __device__ __forceinline__ void cp_wait() {
    asm volatile("cp.async.wait_group %0;" :: "n"(N));
}

// fp32 pair -> bf16x2 hi + lo
__device__ __forceinline__ void pack_hl(float a, float b, uint32_t& hi, uint32_t& lo)
{
    __nv_bfloat162 h = __floats2bfloat162_rn(a, b);
    float ra = a - __bfloat162float(h.x);
    float rb = b - __bfloat162float(h.y);
    __nv_bfloat162 l = __floats2bfloat162_rn(ra, rb);
    hi = *reinterpret_cast<uint32_t*>(&h);
    lo = *reinterpret_cast<uint32_t*>(&l);
}

// fp32 pair -> fp16x2 hi + lo
__device__ __forceinline__ void pack_hl16(float a, float b, uint32_t& hi, uint32_t& lo)
{
    __half2 h = __floats2half2_rn(a, b);
    float ra = a - __half2float(__low2half(h));
    float rb = b - __half2float(__high2half(h));
    __half2 l = __floats2half2_rn(ra, rb);
    hi = *reinterpret_cast<uint32_t*>(&h);
    lo = *reinterpret_cast<uint32_t*>(&l);
}

// fp32 pair -> fp16x2 single
__device__ __forceinline__ uint32_t pack16(float a, float b)
{
    __half2 h = __floats2half2_rn(a, b);
    return *reinterpret_cast<uint32_t*>(&h);
}

// ---------------------------------------------------------------------------
// Fused fp32 -> fp16 (hi, lo) split: all 7 tensors in one launch.
// lo planes skipped for v, Wv, Wo (their consumers are single-term).
// ---------------------------------------------------------------------------
__global__ __launch_bounds__(256) void splitk_all(
    const float* __restrict__ q,  const float* __restrict__ k,
    const float* __restrict__ v,  const float* __restrict__ Wq,
    const float* __restrict__ Wk, const float* __restrict__ Wv,
    const float* __restrict__ Wo)
{
    const size_t total4 = (size_t)(3*NX + 4*NW) / 4;
    for (size_t ch = (size_t)blockIdx.x*blockDim.x + threadIdx.x; ch < total4;
         ch += (size_t)gridDim.x*blockDim.x) {
        const size_t i = ch*4;
        const float* src;
        __half *hi, *lo;
        size_t off;
        bool wantlo;
        if (i < (size_t)3*NX) {
            const int w = (int)(i >> 22);
            off = i & (NX - 1);
            src = (w == 0) ? q : (w == 1) ? k : v;
            hi = g_xh[w]; lo = g_xl[w];
            wantlo = (w < 2);
        } else {
            const size_t j = i - (size_t)3*NX;
            const int w = (int)(j >> 20);
            off = j & (NW - 1);
            src = (w == 0) ? Wq : (w == 1) ? Wk : (w == 2) ? Wv : Wo;
            hi = g_wh[w]; lo = g_wl[w];
            wantlo = (w < 2);
        }
        float4 vv = *(const float4*)(src + off);
        uint32_t h0, l0, h1, l1;
        pack_hl16(vv.x, vv.y, h0, l0);
        pack_hl16(vv.z, vv.w, h1, l1);
        *(uint32_t*)(hi + off)     = h0;
        *(uint32_t*)(hi + off + 2) = h1;
        if (wantlo) {
            *(uint32_t*)(lo + off)     = l0;
            *(uint32_t*)(lo + off + 2) = l1;
        }
    }
}

// ---------------------------------------------------------------------------
// fp16 GEMM: C = A @ W^T + bias.  TERMS=3 (Q,K) or 1 (V, O).
// dst 0/1: bf16 hi/lo -> g_qkvh/l[dst]; dst 2: fp16 -> g_vh; dst 3: fp32 out.
// CTA 128x128, 8 warps (32x64), Kc=32, 3-stage cp.async, 2 CTAs/SM.
// ---------------------------------------------------------------------------
#define GTILE_B   8192             // 128 rows * 64 B
#define GBUF_B    (4*GTILE_B)      // 32768 (Ah,Al,Wh,Wl slots)
#define GEMM_SMEM (3*GBUF_B)       // 98304; x2 CTAs = 196608

__device__ __forceinline__ uint32_t gswz(int row, int c16) {
    return (uint32_t)row*64 + (uint32_t)((c16 ^ ((row >> 1) & 3)) * 16);
}

template<int TERMS>
__device__ __forceinline__ void gemm_fill(
    const __half* const* srcs, uint32_t stage_base, int kc, int srow, int shalf)
{
    const size_t g = (size_t)srow*D_MODEL + kc + shalf*16;
    const uint32_t s0 = stage_base + gswz(srow, shalf*2);
    const uint32_t s1 = stage_base + gswz(srow, shalf*2 + 1);
    #pragma unroll
    for (int t = 0; t < 4; t++) {
        if (TERMS == 1 && (t & 1)) continue;   // skip Al, Wl slots
        cp16(s0 + t*GTILE_B, srcs[t] + g);
        cp16(s1 + t*GTILE_B, srcs[t] + g + 8);
    }
}

template<int TERMS>
__device__ __forceinline__ void gemm_body(
    const __half* Ah, const __half* Al,
    const __half* Wh, const __half* Wl,
    const float* __restrict__ bias,
    float* __restrict__ outp, int dst, int bm, int bn, char* smem)
{
    const uint32_t sm0 = smem_to_u32(smem);
    const int tid  = threadIdx.x;
    const int lane = tid & 31;
    const int wid  = tid >> 5;
    const int wm = wid & 3;
    const int wn = wid >> 2;

    const __half* srcs[4] = {
        Ah + (size_t)bm*128*D_MODEL,
        Al + (size_t)bm*128*D_MODEL,
        Wh + (size_t)bn*128*D_MODEL,
        Wl + (size_t)bn*128*D_MODEL };

    const int srow  = tid >> 1;
    const int shalf = tid & 1;

    gemm_fill<TERMS>(srcs, sm0 + 0*GBUF_B, 0,  srow, shalf);
    cp_commit();
    gemm_fill<TERMS>(srcs, sm0 + 1*GBUF_B, 32, srow, shalf);
    cp_commit();

    const int a_row0 = wm*32 + (lane & 15);
    const int b_row0 = wn*64 + ((lane >> 4) & 1)*8 + (lane & 7);
    const int a_c16h = (lane >> 4) & 1;
    const int b_c16h = (lane >> 3) & 1;

    float acc[2][8][4] = {};

    for (int c = 0; c < 32; c++) {
        cp_wait<1>();
        __syncthreads();

        if (c < 30)
            gemm_fill<TERMS>(srcs, sm0 + ((c + 2) % 3)*GBUF_B, (c + 2)*32, srow, shalf);
        cp_commit();

        const uint32_t base = sm0 + (c % 3)*GBUF_B;
        #pragma unroll
        for (int ks = 0; ks < 2; ks++) {
            uint32_t ah[2][4], al[2][4];
            #pragma unroll
            for (int fm = 0; fm < 2; fm++) {
                const uint32_t ao = gswz(a_row0 + fm*16, ks*2 + a_c16h);
                ldsm_x4(ah[fm], base + 0*GTILE_B + ao);
                if (TERMS == 3) ldsm_x4(al[fm], base + 1*GTILE_B + ao);
            }
            #pragma unroll
            for (int p = 0; p < 4; p++) {
                const uint32_t bo = gswz(b_row0 + p*16, ks*2 + b_c16h);
                uint32_t bh[4], bl[4];
                ldsm_x4(bh, base + 2*GTILE_B + bo);
                if (TERMS == 3) ldsm_x4(bl, base + 3*GTILE_B + bo);
                #pragma unroll
                for (int q = 0; q < 2; q++) {
                    const int fn = p*2 + q;
                    #pragma unroll
                    for (int fm = 0; fm < 2; fm++) {
                        mma16816f(acc[fm][fn], ah[fm], bh + q*2);
                        if (TERMS == 3) {
                            mma16816f(acc[fm][fn], ah[fm], bl + q*2);
                            mma16816f(acc[fm][fn], al[fm], bh + q*2);
                        }
                    }
                }
            }
        }
    }

    // Epilogue
    const int r4 = lane >> 2;
    const int kw = lane & 3;
    #pragma unroll
    for (int fm = 0; fm < 2; fm++) {
        #pragma unroll
        for (int fn = 0; fn < 8; fn++) {
            const int row = bm*128 + wm*32 + fm*16 + r4;
            const int col = bn*128 + wn*64 + fn*8 + kw*2;
            const float b0 = bias[col], b1 = bias[col+1];
            #pragma unroll
            for (int p = 0; p < 2; p++) {
                const int rr = row + p*8;
                const float vx = acc[fm][fn][p*2+0] + b0;
                const float vy = acc[fm][fn][p*2+1] + b1;
                if (dst < 2) {
                    const int b = rr >> 11, s = rr & 2047;
                    const int h = col >> 6, d = col & 63;
                    const size_t idx = (((size_t)(b*HEADS + h))*SEQ + s)*DKH + d;
                    uint32_t hi, lo;
                    pack_hl(vx, vy, hi, lo);              // bf16 pair for flash QK
                    *(uint32_t*)(g_qkvh[dst] + idx) = hi;
                    *(uint32_t*)(g_qkvl[dst] + idx) = lo;
                } else if (dst == 2) {
                    const int b = rr >> 11, s = rr & 2047;
                    const int h = col >> 6, d = col & 63;
                    const size_t idx = (((size_t)(b*HEADS + h))*SEQ + s)*DKH + d;
                    *(uint32_t*)(g_vh + idx) = pack16(vx, vy);   // V fp16 single
                } else {
                    float2 ov; ov.x = vx; ov.y = vy;
                    *(float2*)(outp + (size_t)rr*D_MODEL + col) = ov;
                }
            }
        }
    }
}

// Fused Q,K,V projections: z in {0,1}: 3-term; z==2: V single-term.
__global__ __launch_bounds__(256, 2) void gemm_qkv(
    const float* __restrict__ bq, const float* __restrict__ bk,
    const float* __restrict__ bv)
{
    extern __shared__ char smem[];
    const int z = blockIdx.z;
    if (z < 2) {
        gemm_body<3>(g_xh[z], g_xl[z], g_wh[z], g_wl[z], (z == 0) ? bq : bk,
                     nullptr, z, blockIdx.y, blockIdx.x, smem);
    } else {
        gemm_body<1>(g_xh[2], g_xh[2], g_wh[2], g_wh[2], bv,
                     nullptr, 2, blockIdx.y, blockIdx.x, smem);
    }
}

// Output projection: single-term fp16.
__global__ __launch_bounds__(256, 2) void gemm_out(
    const float* __restrict__ bo, float* __restrict__ outp)
{
    extern __shared__ char smem[];
    gemm_body<1>(g_aoh, g_aoh, g_wh[3], g_wh[3], bo,
                 outp, 3, blockIdx.y, blockIdx.x, smem);
}

// ---------------------------------------------------------------------------
// Flash attention: QK^T 3-term bf16; online softmax; P via h2exp2 (fp16
// exp2, half the MUFU traffic); PV single-term fp16.
// KV smem: Khi, Klo (bf16), V (fp16) — 3 x 8KB per stage, 3 stages.
// ---------------------------------------------------------------------------
#define KVTILE_B   8192                // 64 rows * 128 B
#define KVBUF_B    (3*KVTILE_B)        // 24576 (Khi, Klo, V)
#define FLASH_SMEM (3*KVBUF_B)         // 73728; x2 CTAs = 147456
#define L2E 1.4426950408889634f

__device__ __forceinline__ uint32_t fswz(int row, int c16) {
    return (uint32_t)row*128 + (uint32_t)((c16 ^ (row & 7)) * 16);
}

__global__ __launch_bounds__(256, 2) void flash_mma(void)
{
    extern __shared__ char fsm[];
    const uint32_t sm0 = smem_to_u32(fsm);
    const int tid  = threadIdx.x;
    const int lane = tid & 31;
    const int wid  = tid >> 5;            // 0..7
    const int bh   = blockIdx.y;
    const int q0   = blockIdx.x * 128;
    const int b    = bh >> 4, h = bh & 15;

    const __nv_bfloat16* Qh = g_qkvh[0] + ((size_t)bh*SEQ + q0 + wid*16)*DKH;
    const __nv_bfloat16* Ql = g_qkvl[0] + ((size_t)bh*SEQ + q0 + wid*16)*DKH;
    const __nv_bfloat16* Kh = g_qkvh[1] + (size_t)bh*SEQ*DKH;
    const __nv_bfloat16* Kl = g_qkvl[1] + (size_t)bh*SEQ*DKH;
    const __half*        Vp = g_vh      + (size_t)bh*SEQ*DKH;

    const int r4 = lane >> 2;
    const int kw = lane & 3;

    uint32_t qh[4][4], ql[4][4];
    #pragma unroll
    for (int ks = 0; ks < 4; ks++) {
        const int cb = ks*16 + kw*2;
        qh[ks][0] = *(const uint32_t*)(Qh + (size_t)r4*DKH + cb);
        qh[ks][1] = *(const uint32_t*)(Qh + (size_t)(r4+8)*DKH + cb);
        qh[ks][2] = *(const uint32_t*)(Qh + (size_t)r4*DKH + cb + 8);
        qh[ks][3] = *(const uint32_t*)(Qh + (size_t)(r4+8)*DKH + cb + 8);
        ql[ks][0] = *(const uint32_t*)(Ql + (size_t)r4*DKH + cb);
        ql[ks][1] = *(const uint32_t*)(Ql + (size_t)(r4+8)*DKH + cb);
        ql[ks][2] = *(const uint32_t*)(Ql + (size_t)r4*DKH + cb + 8);
        ql[ks][3] = *(const uint32_t*)(Ql + (size_t)(r4+8)*DKH + cb + 8);
    }

    const int  krow = tid >> 2;
    const int  kq   = tid & 3;
    const size_t gkoff = (size_t)krow*DKH + kq*16;
    const uint32_t s0off = fswz(krow, kq*2);
    const uint32_t s1off = fswz(krow, kq*2 + 1);

    const int k_row0 = ((lane >> 4) & 1)*8 + (lane & 7);
    const int k_c16h = (lane >> 3) & 1;
    const int v_row0 = ((lane >> 3) & 1)*8 + (lane & 7);
    const int v_c16h = (lane >> 4) & 1;

    float accO[8][4] = {};
    float lsum0 = 0.f, lsum1 = 0.f;
    float m0 = -1e30f, m1 = -1e30f;

    #pragma unroll
    for (int ktp = 0; ktp < 2; ktp++) {
        const size_t g = (size_t)ktp*64*DKH + gkoff;
        const uint32_t sb = sm0 + ktp*KVBUF_B;
        cp16(sb + 0*KVTILE_B + s0off, Kh + g);
        cp16(sb + 0*KVTILE_B + s1off, Kh + g + 8);
        cp16(sb + 1*KVTILE_B + s0off, Kl + g);
        cp16(sb + 1*KVTILE_B + s1off, Kl + g + 8);
        cp16(sb + 2*KVTILE_B + s0off, Vp + g);
        cp16(sb + 2*KVTILE_B + s1off, Vp + g + 8);
        cp_commit();
    }

    #pragma unroll 1
    for (int kt = 0; kt < SEQ/64; kt++) {
        cp_wait<1>();
        __syncthreads();

        if (kt < SEQ/64 - 2) {
            const size_t g = (size_t)(kt+2)*64*DKH + gkoff;
            const uint32_t sb = sm0 + ((kt+2) % 3)*KVBUF_B;
            cp16(sb + 0*KVTILE_B + s0off, Kh + g);
            cp16(sb + 0*KVTILE_B + s1off, Kh + g + 8);
            cp16(sb + 1*KVTILE_B + s0off, Kl + g);
            cp16(sb + 1*KVTILE_B + s1off, Kl + g + 8);
            cp16(sb + 2*KVTILE_B + s0off, Vp + g);
            cp16(sb + 2*KVTILE_B + s1off, Vp + g + 8);
        }
        cp_commit();

        const uint32_t base = sm0 + (kt % 3)*KVBUF_B;

        // ---- scores: S = Q K^T (3-term bf16) ----
        float s[8][4] = {};
        #pragma unroll
        for (int ks = 0; ks < 4; ks++) {
            #pragma unroll
            for (int pp = 0; pp < 4; pp += 2) {
                uint32_t bhr[2][4], blr[2][4];
                #pragma unroll
                for (int pi = 0; pi < 2; pi++) {
                    const uint32_t bo = fswz((pp + pi)*16 + k_row0, ks*2 + k_c16h);
                    ldsm_x4(bhr[pi], base + 0*KVTILE_B + bo);
                    ldsm_x4(blr[pi], base + 1*KVTILE_B + bo);
                }
                #pragma unroll
                for (int t = 0; t < 3; t++) {
                    const uint32_t* aa = (t == 2) ? ql[ks] : qh[ks];
                    #pragma unroll
                    for (int pi = 0; pi < 2; pi++) {
                        #pragma unroll
                        for (int q = 0; q < 2; q++) {
                            const uint32_t* bb = (t == 1) ? (blr[pi] + q*2)
                                                          : (bhr[pi] + q*2);
                            mma16816(s[(pp + pi)*2 + q], aa, bb);
                        }
                    }
                }
            }
        }

        // ---- online softmax: running row max + rescale ----
        float tm0 = s[0][0], tm1 = s[0][2];
        #pragma unroll
        for (int f = 0; f < 8; f++) {
            tm0 = fmaxf(tm0, fmaxf(s[f][0], s[f][1]));
            tm1 = fmaxf(tm1, fmaxf(s[f][2], s[f][3]));
        }
        tm0 = fmaxf(tm0, __shfl_xor_sync(0xffffffffu, tm0, 1));
        tm0 = fmaxf(tm0, __shfl_xor_sync(0xffffffffu, tm0, 2));
        tm1 = fmaxf(tm1, __shfl_xor_sync(0xffffffffu, tm1, 1));
        tm1 = fmaxf(tm1, __shfl_xor_sync(0xffffffffu, tm1, 2));
        const float mn0 = fmaxf(m0, tm0);
        const float mn1 = fmaxf(m1, tm1);
        const float c0 = ex2f((m0 - mn0)*L2E);
        const float c1 = ex2f((m1 - mn1)*L2E);
        m0 = mn0; m1 = mn1;
        lsum0 *= c0; lsum1 *= c1;
        #pragma unroll
        for (int f = 0; f < 8; f++) {
            accO[f][0] *= c0; accO[f][1] *= c0;
            accO[f][2] *= c1; accO[f][3] *= c1;
        }
        const float nm0 = -mn0*L2E;
        const float nm1 = -mn1*L2E;

        // ---- P = exp(S - m) via h2exp2; O += P V (single-term fp16) ----
        #pragma unroll
        for (int ks = 0; ks < 4; ks++) {
            const int f0 = 2*ks, f1 = 2*ks + 1;
            __half2 e0 = h2exp2(__floats2half2_rn(fmaf(s[f0][0], L2E, nm0),
                                                  fmaf(s[f0][1], L2E, nm0)));
            __half2 e1 = h2exp2(__floats2half2_rn(fmaf(s[f0][2], L2E, nm1),
                                                  fmaf(s[f0][3], L2E, nm1)));
            __half2 e2 = h2exp2(__floats2half2_rn(fmaf(s[f1][0], L2E, nm0),
                                                  fmaf(s[f1][1], L2E, nm0)));
            __half2 e3 = h2exp2(__floats2half2_rn(fmaf(s[f1][2], L2E, nm1),
                                                  fmaf(s[f1][3], L2E, nm1)));
            float2 v0 = __half22float2(e0); lsum0 += v0.x + v0.y;
            float2 v1 = __half22float2(e1); lsum1 += v1.x + v1.y;
            float2 v2 = __half22float2(e2); lsum0 += v2.x + v2.y;
            float2 v3 = __half22float2(e3); lsum1 += v3.x + v3.y;
            uint32_t pa[4];
            pa[0] = *reinterpret_cast<uint32_t*>(&e0);
            pa[1] = *reinterpret_cast<uint32_t*>(&e1);
            pa[2] = *reinterpret_cast<uint32_t*>(&e2);
            pa[3] = *reinterpret_cast<uint32_t*>(&e3);
            #pragma unroll
            for (int p = 0; p < 4; p++) {
                const uint32_t vo = fswz(ks*16 + v_row0, p*2 + v_c16h);
                uint32_t vr[4];
                ldsm_x4_t(vr, base + 2*KVTILE_B + vo);
                mma16816f(accO[p*2 + 0], pa, vr + 0);
                mma16816f(accO[p*2 + 1], pa, vr + 2);
            }
        }
    }

    lsum0 += __shfl_xor_sync(0xffffffffu, lsum0, 1);
    lsum0 += __shfl_xor_sync(0xffffffffu, lsum0, 2);
    lsum1 += __shfl_xor_sync(0xffffffffu, lsum1, 1);
    lsum1 += __shfl_xor_sync(0xffffffffu, lsum1, 2);
    const float inv0 = 1.f / lsum0;
    const float inv1 = 1.f / lsum1;

    const size_t obase = ((size_t)b*SEQ + q0 + wid*16)*D_MODEL + h*DKH;
    #pragma unroll
    for (int f = 0; f < 8; f++) {
        const int d = f*8 + kw*2;
        *(uint32_t*)(g_aoh + obase + (size_t)r4*D_MODEL + d) =
            pack16(accO[f][0]*inv0, accO[f][1]*inv0);
        *(uint32_t*)(g_aoh + obase + (size_t)(r4+8)*D_MODEL + d) =
            pack16(accO[f][2]*inv1, accO[f][3]*inv1);
    }
}

// ---------------------------------------------------------------------------
// Launch
// ---------------------------------------------------------------------------
extern "C" void kernel_launch(void* const* d_in, const int* in_sizes, int n_in,
                              void* d_out, int out_size)
{
    const float* q  = (const float*)d_in[0];
    const float* k  = (const float*)d_in[1];
    const float* v  = (const float*)d_in[2];
    const float* Wq = (const float*)d_in[3];
    const float* bq = (const float*)d_in[4];
    const float* Wk = (const float*)d_in[5];
    const float* bk = (const float*)d_in[6];
    const float* Wv = (const float*)d_in[7];
    const float* bv = (const float*)d_in[8];
    const float* Wo = (const float*)d_in[9];
    const float* bo = (const float*)d_in[10];
    float* out = (float*)d_out;

    cudaFuncSetAttribute(gemm_qkv,  cudaFuncAttributeMaxDynamicSharedMemorySize, GEMM_SMEM);
    cudaFuncSetAttribute(gemm_out,  cudaFuncAttributeMaxDynamicSharedMemorySize, GEMM_SMEM);
    cudaFuncSetAttribute(flash_mma, cudaFuncAttributeMaxDynamicSharedMemorySize, FLASH_SMEM);

    splitk_all<<<8192, 256>>>(q, k, v, Wq, Wk, Wv, Wo);

    gemm_qkv<<<dim3(D_MODEL/128, MROWS/128, 3), 256, GEMM_SMEM>>>(bq, bk, bv);

    flash_mma<<<dim3(SEQ/128, BATCH*HEADS), 256, FLASH_SMEM>>>();

    gemm_out<<<dim3(D_MODEL/128, MROWS/128), 256, GEMM_SMEM>>>(bo, out);
}

// round 17
// speedup vs baseline: 1.7246x; 1.0038x over previous
#include <cuda_runtime.h>
#include <cuda_bf16.h>
#include <cuda_fp16.h>
#include <cstdint>

// Problem constants
#define D_MODEL 1024
#define SEQ     2048
#define BATCH   2
#define HEADS   16
#define DKH     64
#define MROWS   (BATCH*SEQ)          // 4096
#define NX      (MROWS*D_MODEL)      // 2^22
#define NW      (D_MODEL*D_MODEL)    // 2^20

// ---------------------------------------------------------------------------
// Scratch (device globals — no allocation allowed)
// ---------------------------------------------------------------------------
__device__ __half g_xh[3][NX];                    // q,k,v inputs fp16 hi
__device__ __half g_xl[3][NX];                    // fp16 lo (lo unused for v)
__device__ __half g_wh[4][NW];
__device__ __half g_wl[4][NW];                    // lo unused for Wv, Wo
__device__ __nv_bfloat16 g_qkvh[2][BATCH*HEADS*SEQ*DKH];  // Q/K bf16 hi (flash)
__device__ __nv_bfloat16 g_qkvl[2][BATCH*HEADS*SEQ*DKH];  // Q/K bf16 lo
__device__ __half g_vh[BATCH*HEADS*SEQ*DKH];      // V fp16 single
__device__ __half g_aoh[NX];                      // attention out fp16 single

// ---------------------------------------------------------------------------
// PTX helpers
// ---------------------------------------------------------------------------
__device__ __forceinline__ uint32_t smem_to_u32(const void* p) {
    uint32_t a;
    asm("{ .reg .u64 t; cvta.to.shared.u64 t, %1; cvt.u32.u64 %0, t; }"
        : "=r"(a) : "l"(p));
    return a;
}

__device__ __forceinline__ float ex2f(float x) {
    float r;
    asm("ex2.approx.f32 %0, %1;" : "=f"(r) : "f"(x));
    return r;
}

// bf16 MMA, f32 acc (flash QK^T)
__device__ __forceinline__ void mma16816(float* c, const uint32_t* a, const uint32_t* b)
{
    asm volatile(
        "mma.sync.aligned.m16n8k16.row.col.f32.bf16.bf16.f32 "
        "{%0,%1,%2,%3}, {%4,%5,%6,%7}, {%8,%9}, {%0,%1,%2,%3};"
        : "+f"(c[0]), "+f"(c[1]), "+f"(c[2]), "+f"(c[3])
        : "r"(a[0]), "r"(a[1]), "r"(a[2]), "r"(a[3]), "r"(b[0]), "r"(b[1]));
}

// fp16 MMA, f32 acc (projections + flash PV)
__device__ __forceinline__ void mma16816f(float* c, const uint32_t* a, const uint32_t* b)
{
    asm volatile(
        "mma.sync.aligned.m16n8k16.row.col.f32.f16.f16.f32 "
        "{%0,%1,%2,%3}, {%4,%5,%6,%7}, {%8,%9}, {%0,%1,%2,%3};"
        : "+f"(c[0]), "+f"(c[1]), "+f"(c[2]), "+f"(c[3])
        : "r"(a[0]), "r"(a[1]), "r"(a[2]), "r"(a[3]), "r"(b[0]), "r"(b[1]));
}

__device__ __forceinline__ void ldsm_x4(uint32_t* r, uint32_t addr)
{
    asm volatile("ldmatrix.sync.aligned.m8n8.x4.shared.b16 {%0,%1,%2,%3}, [%4];"
        : "=r"(r[0]), "=r"(r[1]), "=r"(r[2]), "=r"(r[3]) : "r"(addr));
}

__device__ __forceinline__ void ldsm_x4_t(uint32_t* r, uint32_t addr)
{
    asm volatile("ldmatrix.sync.aligned.m8n8.x4.trans.shared.b16 {%0,%1,%2,%3}, [%4];"
        : "=r"(r[0]), "=r"(r[1]), "=r"(r[2]), "=r"(r[3]) : "r"(addr));
}

__device__ __forceinline__ void cp16(uint32_t saddr, const void* g) {
    asm volatile("cp.async.cg.shared.global [%0], [%1], 16;" :: "r"(saddr), "l"(g));
}
__device__ __forceinline__ void cp_commit() {
    asm volatile("cp.async.commit_group;");
}
template<int N> __device__ __forceinline__ void cp_wait() {
    asm volatile("cp.async.wait_group %0;" :: "n"(N));
}

// fp32 pair -> bf16x2 hi + lo
__device__ __forceinline__ void pack_hl(float a, float b, uint32_t& hi, uint32_t& lo)
{
    __nv_bfloat162 h = __floats2bfloat162_rn(a, b);
    float ra = a - __bfloat162float(h.x);
    float rb = b - __bfloat162float(h.y);
    __nv_bfloat162 l = __floats2bfloat162_rn(ra, rb);
    hi = *reinterpret_cast<uint32_t*>(&h);
    lo = *reinterpret_cast<uint32_t*>(&l);
}

// fp32 pair -> fp16x2 hi + lo
__device__ __forceinline__ void pack_hl16(float a, float b, uint32_t& hi, uint32_t& lo)
{
    __half2 h = __floats2half2_rn(a, b);
    float ra = a - __half2float(__low2half(h));
    float rb = b - __half2float(__high2half(h));
    __half2 l = __floats2half2_rn(ra, rb);
    hi = *reinterpret_cast<uint32_t*>(&h);
    lo = *reinterpret_cast<uint32_t*>(&l);
}

// fp32 pair -> fp16x2 single
__device__ __forceinline__ uint32_t pack16(float a, float b)
{
    __half2 h = __floats2half2_rn(a, b);
    return *reinterpret_cast<uint32_t*>(&h);
}

// ---------------------------------------------------------------------------
// Fused fp32 -> fp16 (hi, lo) split: all 7 tensors in one launch.
// lo planes skipped for v, Wv, Wo (their consumers are single-term).
// ---------------------------------------------------------------------------
__global__ __launch_bounds__(256) void splitk_all(
    const float* __restrict__ q,  const float* __restrict__ k,
    const float* __restrict__ v,  const float* __restrict__ Wq,
    const float* __restrict__ Wk, const float* __restrict__ Wv,
    const float* __restrict__ Wo)
{
    const size_t total4 = (size_t)(3*NX + 4*NW) / 4;
    for (size_t ch = (size_t)blockIdx.x*blockDim.x + threadIdx.x; ch < total4;
         ch += (size_t)gridDim.x*blockDim.x) {
        const size_t i = ch*4;
        const float* src;
        __half *hi, *lo;
        size_t off;
        bool wantlo;
        if (i < (size_t)3*NX) {
            const int w = (int)(i >> 22);
            off = i & (NX - 1);
            src = (w == 0) ? q : (w == 1) ? k : v;
            hi = g_xh[w]; lo = g_xl[w];
            wantlo = (w < 2);
        } else {
            const size_t j = i - (size_t)3*NX;
            const int w = (int)(j >> 20);
            off = j & (NW - 1);
            src = (w == 0) ? Wq : (w == 1) ? Wk : (w == 2) ? Wv : Wo;
            hi = g_wh[w]; lo = g_wl[w];
            wantlo = (w < 2);
        }
        float4 vv = *(const float4*)(src + off);
        uint32_t h0, l0, h1, l1;
        pack_hl16(vv.x, vv.y, h0, l0);
        pack_hl16(vv.z, vv.w, h1, l1);
        *(uint32_t*)(hi + off)     = h0;
        *(uint32_t*)(hi + off + 2) = h1;
        if (wantlo) {
            *(uint32_t*)(lo + off)     = l0;
            *(uint32_t*)(lo + off + 2) = l1;
        }
    }
}

// ---------------------------------------------------------------------------
// fp16 GEMM: C = A @ W^T + bias.
// TERMS=3: Kc=32, slots {Ah,Al,Wh,Wl}, 3 MMA terms (Q,K proj).
// TERMS=1: Kc=64, slots {A k0,A k1,W k0,W k1}, 1 MMA term (V, O proj) —
//          half the barriers, 2x MMAs per chunk; K order unchanged so
//          numerics are bit-identical to the R16 version.
// CTA 128x128, 8 warps (32x64), 3-stage cp.async, 2 CTAs/SM.
// ---------------------------------------------------------------------------
#define GTILE_B   8192             // 128 rows * 64 B
#define GBUF_B    (4*GTILE_B)      // 32768 (4 slots)
#define GEMM_SMEM (3*GBUF_B)       // 98304; x2 CTAs = 196608

__device__ __forceinline__ uint32_t gswz(int row, int c16) {
    return (uint32_t)row*64 + (uint32_t)((c16 ^ ((row >> 1) & 3)) * 16);
}

template<int TERMS>
__device__ __forceinline__ void gemm_fill(
    const __half* const* srcs, uint32_t stage_base, int kc, int srow, int shalf)
{
    const uint32_t o0 = gswz(srow, shalf*2);
    const uint32_t o1 = gswz(srow, shalf*2 + 1);
    if (TERMS == 3) {
        const size_t g = (size_t)srow*D_MODEL + kc + shalf*16;
        #pragma unroll
        for (int t = 0; t < 4; t++) {
            cp16(stage_base + t*GTILE_B + o0, srcs[t] + g);
            cp16(stage_base + t*GTILE_B + o1, srcs[t] + g + 8);
        }
    } else {
        // slots 0,1 = A k-halves; slots 2,3 = W k-halves (Kc = 64)
        const size_t g = (size_t)srow*D_MODEL + kc + shalf*16;
        #pragma unroll
        for (int half = 0; half < 2; half++) {
            cp16(stage_base + half*GTILE_B + o0,       srcs[0] + g + half*32);
            cp16(stage_base + half*GTILE_B + o1,       srcs[0] + g + half*32 + 8);
            cp16(stage_base + (2+half)*GTILE_B + o0,   srcs[2] + g + half*32);
            cp16(stage_base + (2+half)*GTILE_B + o1,   srcs[2] + g + half*32 + 8);
        }
    }
}

template<int TERMS>
__device__ __forceinline__ void gemm_body(
    const __half* Ah, const __half* Al,
    const __half* Wh, const __half* Wl,
    const float* __restrict__ bias,
    float* __restrict__ outp, int dst, int bm, int bn, char* smem)
{
    const uint32_t sm0 = smem_to_u32(smem);
    const int tid  = threadIdx.x;
    const int lane = tid & 31;
    const int wid  = tid >> 5;
    const int wm = wid & 3;
    const int wn = wid >> 2;

    const __half* srcs[4] = {
        Ah + (size_t)bm*128*D_MODEL,
        Al + (size_t)bm*128*D_MODEL,
        Wh + (size_t)bn*128*D_MODEL,
        Wl + (size_t)bn*128*D_MODEL };

    const int srow  = tid >> 1;
    const int shalf = tid & 1;

    constexpr int KCH    = (TERMS == 3) ? 32 : 64;
    constexpr int NCHUNK = D_MODEL / KCH;
    constexpr int KSUB   = KCH / 32;

    gemm_fill<TERMS>(srcs, sm0 + 0*GBUF_B, 0,   srow, shalf);
    cp_commit();
    gemm_fill<TERMS>(srcs, sm0 + 1*GBUF_B, KCH, srow, shalf);
    cp_commit();

    const int a_row0 = wm*32 + (lane & 15);
    const int b_row0 = wn*64 + ((lane >> 4) & 1)*8 + (lane & 7);
    const int a_c16h = (lane >> 4) & 1;
    const int b_c16h = (lane >> 3) & 1;

    float acc[2][8][4] = {};

    for (int c = 0; c < NCHUNK; c++) {
        cp_wait<1>();
        __syncthreads();

        if (c < NCHUNK - 2)
            gemm_fill<TERMS>(srcs, sm0 + ((c + 2) % 3)*GBUF_B, (c + 2)*KCH, srow, shalf);
        cp_commit();

        const uint32_t base = sm0 + (c % 3)*GBUF_B;
        #pragma unroll
        for (int sub = 0; sub < KSUB; sub++) {
            const uint32_t abase = base + ((TERMS == 3) ? 0 : sub)*GTILE_B;
            const uint32_t wbase = base + ((TERMS == 3) ? 2 : 2 + sub)*GTILE_B;
            #pragma unroll
            for (int ks = 0; ks < 2; ks++) {
                uint32_t ah[2][4], al[2][4];
                #pragma unroll
                for (int fm = 0; fm < 2; fm++) {
                    const uint32_t ao = gswz(a_row0 + fm*16, ks*2 + a_c16h);
                    ldsm_x4(ah[fm], abase + ao);
                    if (TERMS == 3) ldsm_x4(al[fm], base + 1*GTILE_B + ao);
                }
                #pragma unroll
                for (int p = 0; p < 4; p++) {
                    const uint32_t bo = gswz(b_row0 + p*16, ks*2 + b_c16h);
                    uint32_t bh[4], bl[4];
                    ldsm_x4(bh, wbase + bo);
                    if (TERMS == 3) ldsm_x4(bl, base + 3*GTILE_B + bo);
                    #pragma unroll
                    for (int q = 0; q < 2; q++) {
                        const int fn = p*2 + q;
                        #pragma unroll
                        for (int fm = 0; fm < 2; fm++) {
                            mma16816f(acc[fm][fn], ah[fm], bh + q*2);
                            if (TERMS == 3) {
                                mma16816f(acc[fm][fn], ah[fm], bl + q*2);
                                mma16816f(acc[fm][fn], al[fm], bh + q*2);
                            }
                        }
                    }
                }
            }
        }
    }

    // Epilogue
    const int r4 = lane >> 2;
    const int kw = lane & 3;
    #pragma unroll
    for (int fm = 0; fm < 2; fm++) {
        #pragma unroll
        for (int fn = 0; fn < 8; fn++) {
            const int row = bm*128 + wm*32 + fm*16 + r4;
            const int col = bn*128 + wn*64 + fn*8 + kw*2;
            const float b0 = bias[col], b1 = bias[col+1];
            #pragma unroll
            for (int p = 0; p < 2; p++) {
                const int rr = row + p*8;
                const float vx = acc[fm][fn][p*2+0] + b0;
                const float vy = acc[fm][fn][p*2+1] + b1;
                if (dst < 2) {
                    const int b = rr >> 11, s = rr & 2047;
                    const int h = col >> 6, d = col & 63;
                    const size_t idx = (((size_t)(b*HEADS + h))*SEQ + s)*DKH + d;
                    uint32_t hi, lo;
                    pack_hl(vx, vy, hi, lo);              // bf16 pair for flash QK
                    *(uint32_t*)(g_qkvh[dst] + idx) = hi;
                    *(uint32_t*)(g_qkvl[dst] + idx) = lo;
                } else if (dst == 2) {
                    const int b = rr >> 11, s = rr & 2047;
                    const int h = col >> 6, d = col & 63;
                    const size_t idx = (((size_t)(b*HEADS + h))*SEQ + s)*DKH + d;
                    *(uint32_t*)(g_vh + idx) = pack16(vx, vy);   // V fp16 single
                } else {
                    float2 ov; ov.x = vx; ov.y = vy;
                    *(float2*)(outp + (size_t)rr*D_MODEL + col) = ov;
                }
            }
        }
    }
}

// Fused Q,K,V projections: z in {0,1}: 3-term; z==2: V single-term.
__global__ __launch_bounds__(256, 2) void gemm_qkv(
    const float* __restrict__ bq, const float* __restrict__ bk,
    const float* __restrict__ bv)
{
    extern __shared__ char smem[];
    const int z = blockIdx.z;
    if (z < 2) {
        gemm_body<3>(g_xh[z], g_xl[z], g_wh[z], g_wl[z], (z == 0) ? bq : bk,
                     nullptr, z, blockIdx.y, blockIdx.x, smem);
    } else {
        gemm_body<1>(g_xh[2], g_xh[2], g_wh[2], g_wh[2], bv,
                     nullptr, 2, blockIdx.y, blockIdx.x, smem);
    }
}

// Output projection: single-term fp16.
__global__ __launch_bounds__(256, 2) void gemm_out(
    const float* __restrict__ bo, float* __restrict__ outp)
{
    extern __shared__ char smem[];
    gemm_body<1>(g_aoh, g_aoh, g_wh[3], g_wh[3], bo,
                 outp, 3, blockIdx.y, blockIdx.x, smem);
}

// ---------------------------------------------------------------------------
// Flash attention (validated R16): QK^T 3-term bf16; online softmax; P via
// h2exp2; PV single-term fp16.  KV smem: Khi, Klo, V — 3 stages.
// ---------------------------------------------------------------------------
#define KVTILE_B   8192                // 64 rows * 128 B
#define KVBUF_B    (3*KVTILE_B)        // 24576 (Khi, Klo, V)
#define FLASH_SMEM (3*KVBUF_B)         // 73728; x2 CTAs = 147456
#define L2E 1.4426950408889634f

__device__ __forceinline__ uint32_t fswz(int row, int c16) {
    return (uint32_t)row*128 + (uint32_t)((c16 ^ (row & 7)) * 16);
}

__global__ __launch_bounds__(256, 2) void flash_mma(void)
{
    extern __shared__ char fsm[];
    const uint32_t sm0 = smem_to_u32(fsm);
    const int tid  = threadIdx.x;
    const int lane = tid & 31;
    const int wid  = tid >> 5;            // 0..7
    const int bh   = blockIdx.y;
    const int q0   = blockIdx.x * 128;
    const int b    = bh >> 4, h = bh & 15;

    const __nv_bfloat16* Qh = g_qkvh[0] + ((size_t)bh*SEQ + q0 + wid*16)*DKH;
    const __nv_bfloat16* Ql = g_qkvl[0] + ((size_t)bh*SEQ + q0 + wid*16)*DKH;
    const __nv_bfloat16* Kh = g_qkvh[1] + (size_t)bh*SEQ*DKH;
    const __nv_bfloat16* Kl = g_qkvl[1] + (size_t)bh*SEQ*DKH;
    const __half*        Vp = g_vh      + (size_t)bh*SEQ*DKH;

    const int r4 = lane >> 2;
    const int kw = lane & 3;

    uint32_t qh[4][4], ql[4][4];
    #pragma unroll
    for (int ks = 0; ks < 4; ks++) {
        const int cb = ks*16 + kw*2;
        qh[ks][0] = *(const uint32_t*)(Qh + (size_t)r4*DKH + cb);
        qh[ks][1] = *(const uint32_t*)(Qh + (size_t)(r4+8)*DKH + cb);
        qh[ks][2] = *(const uint32_t*)(Qh + (size_t)r4*DKH + cb + 8);
        qh[ks][3] = *(const uint32_t*)(Qh + (size_t)(r4+8)*DKH + cb + 8);
        ql[ks][0] = *(const uint32_t*)(Ql + (size_t)r4*DKH + cb);
        ql[ks][1] = *(const uint32_t*)(Ql + (size_t)(r4+8)*DKH + cb);
        ql[ks][2] = *(const uint32_t*)(Ql + (size_t)r4*DKH + cb + 8);
        ql[ks][3] = *(const uint32_t*)(Ql + (size_t)(r4+8)*DKH + cb + 8);
    }

    const int  krow = tid >> 2;
    const int  kq   = tid & 3;
    const size_t gkoff = (size_t)krow*DKH + kq*16;
    const uint32_t s0off = fswz(krow, kq*2);
    const uint32_t s1off = fswz(krow, kq*2 + 1);

    const int k_row0 = ((lane >> 4) & 1)*8 + (lane & 7);
    const int k_c16h = (lane >> 3) & 1;
    const int v_row0 = ((lane >> 3) & 1)*8 + (lane & 7);
    const int v_c16h = (lane >> 4) & 1;

    float accO[8][4] = {};
    float lsum0 = 0.f, lsum1 = 0.f;
    float m0 = -1e30f, m1 = -1e30f;

    #pragma unroll
    for (int ktp = 0; ktp < 2; ktp++) {
        const size_t g = (size_t)ktp*64*DKH + gkoff;
        const uint32_t sb = sm0 + ktp*KVBUF_B;
        cp16(sb + 0*KVTILE_B + s0off, Kh + g);
        cp16(sb + 0*KVTILE_B + s1off, Kh + g + 8);
        cp16(sb + 1*KVTILE_B + s0off, Kl + g);
        cp16(sb + 1*KVTILE_B + s1off, Kl + g + 8);
        cp16(sb + 2*KVTILE_B + s0off, Vp + g);
        cp16(sb + 2*KVTILE_B + s1off, Vp + g + 8);
        cp_commit();
    }

    #pragma unroll 1
    for (int kt = 0; kt < SEQ/64; kt++) {
        cp_wait<1>();
        __syncthreads();

        if (kt < SEQ/64 - 2) {
            const size_t g = (size_t)(kt+2)*64*DKH + gkoff;
            const uint32_t sb = sm0 + ((kt+2) % 3)*KVBUF_B;
            cp16(sb + 0*KVTILE_B + s0off, Kh + g);
            cp16(sb + 0*KVTILE_B + s1off, Kh + g + 8);
            cp16(sb + 1*KVTILE_B + s0off, Kl + g);
            cp16(sb + 1*KVTILE_B + s1off, Kl + g + 8);
            cp16(sb + 2*KVTILE_B + s0off, Vp + g);
            cp16(sb + 2*KVTILE_B + s1off, Vp + g + 8);
        }
        cp_commit();

        const uint32_t base = sm0 + (kt % 3)*KVBUF_B;

        // ---- scores: S = Q K^T (3-term bf16) ----
        float s[8][4] = {};
        #pragma unroll
        for (int ks = 0; ks < 4; ks++) {
            #pragma unroll
            for (int pp = 0; pp < 4; pp += 2) {
                uint32_t bhr[2][4], blr[2][4];
                #pragma unroll
                for (int pi = 0; pi < 2; pi++) {
                    const uint32_t bo = fswz((pp + pi)*16 + k_row0, ks*2 + k_c16h);
                    ldsm_x4(bhr[pi], base + 0*KVTILE_B + bo);
                    ldsm_x4(blr[pi], base + 1*KVTILE_B + bo);
                }
                #pragma unroll
                for (int t = 0; t < 3; t++) {
                    const uint32_t* aa = (t == 2) ? ql[ks] : qh[ks];
                    #pragma unroll
                    for (int pi = 0; pi < 2; pi++) {
                        #pragma unroll
                        for (int q = 0; q < 2; q++) {
                            const uint32_t* bb = (t == 1) ? (blr[pi] + q*2)
                                                          : (bhr[pi] + q*2);
                            mma16816(s[(pp + pi)*2 + q], aa, bb);
                        }
                    }
                }
            }
        }

        // ---- online softmax: running row max + rescale ----
        float tm0 = s[0][0], tm1 = s[0][2];
        #pragma unroll
        for (int f = 0; f < 8; f++) {
            tm0 = fmaxf(tm0, fmaxf(s[f][0], s[f][1]));
            tm1 = fmaxf(tm1, fmaxf(s[f][2], s[f][3]));
        }
        tm0 = fmaxf(tm0, __shfl_xor_sync(0xffffffffu, tm0, 1));
        tm0 = fmaxf(tm0, __shfl_xor_sync(0xffffffffu, tm0, 2));
        tm1 = fmaxf(tm1, __shfl_xor_sync(0xffffffffu, tm1, 1));
        tm1 = fmaxf(tm1, __shfl_xor_sync(0xffffffffu, tm1, 2));
        const float mn0 = fmaxf(m0, tm0);
        const float mn1 = fmaxf(m1, tm1);
        const float c0 = ex2f((m0 - mn0)*L2E);
        const float c1 = ex2f((m1 - mn1)*L2E);
        m0 = mn0; m1 = mn1;
        lsum0 *= c0; lsum1 *= c1;
        #pragma unroll
        for (int f = 0; f < 8; f++) {
            accO[f][0] *= c0; accO[f][1] *= c0;
            accO[f][2] *= c1; accO[f][3] *= c1;
        }
        const float nm0 = -mn0*L2E;
        const float nm1 = -mn1*L2E;

        // ---- P = exp(S - m) via h2exp2; O += P V (single-term fp16) ----
        #pragma unroll
        for (int ks = 0; ks < 4; ks++) {
            const int f0 = 2*ks, f1 = 2*ks + 1;
            __half2 e0 = h2exp2(__floats2half2_rn(fmaf(s[f0][0], L2E, nm0),
                                                  fmaf(s[f0][1], L2E, nm0)));
            __half2 e1 = h2exp2(__floats2half2_rn(fmaf(s[f0][2], L2E, nm1),
                                                  fmaf(s[f0][3], L2E, nm1)));
            __half2 e2 = h2exp2(__floats2half2_rn(fmaf(s[f1][0], L2E, nm0),
                                                  fmaf(s[f1][1], L2E, nm0)));
            __half2 e3 = h2exp2(__floats2half2_rn(fmaf(s[f1][2], L2E, nm1),
                                                  fmaf(s[f1][3], L2E, nm1)));
            float2 v0 = __half22float2(e0); lsum0 += v0.x + v0.y;
            float2 v1 = __half22float2(e1); lsum1 += v1.x + v1.y;
            float2 v2 = __half22float2(e2); lsum0 += v2.x + v2.y;
            float2 v3 = __half22float2(e3); lsum1 += v3.x + v3.y;
            uint32_t pa[4];
            pa[0] = *reinterpret_cast<uint32_t*>(&e0);
            pa[1] = *reinterpret_cast<uint32_t*>(&e1);
            pa[2] = *reinterpret_cast<uint32_t*>(&e2);
            pa[3] = *reinterpret_cast<uint32_t*>(&e3);
            #pragma unroll
            for (int p = 0; p < 4; p++) {
                const uint32_t vo = fswz(ks*16 + v_row0, p*2 + v_c16h);
                uint32_t vr[4];
                ldsm_x4_t(vr, base + 2*KVTILE_B + vo);
                mma16816f(accO[p*2 + 0], pa, vr + 0);
                mma16816f(accO[p*2 + 1], pa, vr + 2);
            }
        }
    }

    lsum0 += __shfl_xor_sync(0xffffffffu, lsum0, 1);
    lsum0 += __shfl_xor_sync(0xffffffffu, lsum0, 2);
    lsum1 += __shfl_xor_sync(0xffffffffu, lsum1, 1);
    lsum1 += __shfl_xor_sync(0xffffffffu, lsum1, 2);
    const float inv0 = 1.f / lsum0;
    const float inv1 = 1.f / lsum1;

    const size_t obase = ((size_t)b*SEQ + q0 + wid*16)*D_MODEL + h*DKH;
    #pragma unroll
    for (int f = 0; f < 8; f++) {
        const int d = f*8 + kw*2;
        *(uint32_t*)(g_aoh + obase + (size_t)r4*D_MODEL + d) =
            pack16(accO[f][0]*inv0, accO[f][1]*inv0);
        *(uint32_t*)(g_aoh + obase + (size_t)(r4+8)*D_MODEL + d) =
            pack16(accO[f][2]*inv1, accO[f][3]*inv1);
    }
}

// ---------------------------------------------------------------------------
// Launch
// ---------------------------------------------------------------------------
extern "C" void kernel_launch(void* const* d_in, const int* in_sizes, int n_in,
                              void* d_out, int out_size)
{
    const float* q  = (const float*)d_in[0];
    const float* k  = (const float*)d_in[1];
    const float* v  = (const float*)d_in[2];
    const float* Wq = (const float*)d_in[3];
    const float* bq = (const float*)d_in[4];
    const float* Wk = (const float*)d_in[5];
    const float* bk = (const float*)d_in[6];
    const float* Wv = (const float*)d_in[7];
    const float* bv = (const float*)d_in[8];
    const float* Wo = (const float*)d_in[9];
    const float* bo = (const float*)d_in[10];
    float* out = (float*)d_out;

    cudaFuncSetAttribute(gemm_qkv,  cudaFuncAttributeMaxDynamicSharedMemorySize, GEMM_SMEM);
    cudaFuncSetAttribute(gemm_out,  cudaFuncAttributeMaxDynamicSharedMemorySize, GEMM_SMEM);
    cudaFuncSetAttribute(flash_mma, cudaFuncAttributeMaxDynamicSharedMemorySize, FLASH_SMEM);

    splitk_all<<<8192, 256>>>(q, k, v, Wq, Wk, Wv, Wo);

    gemm_qkv<<<dim3(D_MODEL/128, MROWS/128, 3), 256, GEMM_SMEM>>>(bq, bk, bv);

    flash_mma<<<dim3(SEQ/128, BATCH*HEADS), 256, FLASH_SMEM>>>();

    gemm_out<<<dim3(D_MODEL/128, MROWS/128), 256, GEMM_SMEM>>>(bo, out);
}